// round 6
// baseline (speedup 1.0000x reference)
#include <cuda_runtime.h>
#include <cuda_bf16.h>
#include <math.h>
#include <stdint.h>

typedef __nv_bfloat16  bf16;
typedef __nv_bfloat162 bf162;

// ---------------------------------------------------------------------------
// Problem constants
// ---------------------------------------------------------------------------
#define E_DIM   1024
#define H_NUM   16
#define HD_DIM  64
#define F_DIM   4096
#define B_NUM   4
#define S_LEN   2048
#define N_TOK   (B_NUM * S_LEN)      // 8192
#define BH_NUM  (B_NUM * H_NUM)      // 64
#define LN_EPS  1e-5f

// ---------------------------------------------------------------------------
// Scratch buffers (static device globals) — total ~1.43 GB (< 2GB reloc limit)
// ---------------------------------------------------------------------------
__device__ float g_P   [(size_t)BH_NUM * S_LEN * S_LEN];   // 1 GB; post-softmax
                                                           // holds bf16 hi/lo rows
__device__ float g_res1[(size_t)N_TOK * E_DIM];            // 32 MB (also V fp32)
__device__ float g_h   [(size_t)N_TOK * E_DIM];
__device__ float g_res2[(size_t)N_TOK * E_DIM];
__device__ bf16 g_xh [(size_t)N_TOK * E_DIM],  g_xl [(size_t)N_TOK * E_DIM];
__device__ bf16 g_Wqh[(size_t)E_DIM * E_DIM],  g_Wql[(size_t)E_DIM * E_DIM];
__device__ bf16 g_Wkh[(size_t)E_DIM * E_DIM],  g_Wkl[(size_t)E_DIM * E_DIM];
__device__ bf16 g_Wvh[(size_t)E_DIM * E_DIM],  g_Wvl[(size_t)E_DIM * E_DIM];
__device__ bf16 g_Woh[(size_t)E_DIM * E_DIM],  g_Wol[(size_t)E_DIM * E_DIM];
__device__ bf16 g_W1h[(size_t)F_DIM * E_DIM],  g_W1l[(size_t)F_DIM * E_DIM];
__device__ bf16 g_W2h[(size_t)E_DIM * F_DIM],  g_W2l[(size_t)E_DIM * F_DIM];
__device__ bf16 g_Qh [(size_t)N_TOK * E_DIM],  g_Ql [(size_t)N_TOK * E_DIM];
__device__ bf16 g_Kh [(size_t)N_TOK * E_DIM],  g_Kl [(size_t)N_TOK * E_DIM];
__device__ bf16 g_Vth[(size_t)BH_NUM * HD_DIM * S_LEN], g_Vtl[(size_t)BH_NUM * HD_DIM * S_LEN];
__device__ bf16 g_ah [(size_t)N_TOK * E_DIM],  g_al [(size_t)N_TOK * E_DIM];
__device__ bf16 g_hh [(size_t)N_TOK * E_DIM],  g_hl [(size_t)N_TOK * E_DIM];
__device__ bf16 g_fh [(size_t)N_TOK * F_DIM],  g_fl [(size_t)N_TOK * F_DIM];

// ---------------------------------------------------------------------------
// Helpers
// ---------------------------------------------------------------------------
__device__ __forceinline__ void split1(float v, bf16& h, bf16& l) {
    h = __float2bfloat16(v);
    l = __float2bfloat16(v - __bfloat162float(h));
}

__device__ __forceinline__ uint32_t smem_u32(const void* p) {
    return (uint32_t)__cvta_generic_to_shared(p);
}

__device__ __forceinline__ void ldsm4(uint32_t* r, uint32_t a) {
    asm volatile("ldmatrix.sync.aligned.m8n8.x4.shared.b16 {%0,%1,%2,%3}, [%4];"
        : "=r"(r[0]), "=r"(r[1]), "=r"(r[2]), "=r"(r[3]) : "r"(a));
}

__device__ __forceinline__ void mma16816(float* c, const uint32_t* a, const uint32_t* b) {
    asm volatile(
        "mma.sync.aligned.m16n8k16.row.col.f32.bf16.bf16.f32 "
        "{%0,%1,%2,%3}, {%4,%5,%6,%7}, {%8,%9}, {%0,%1,%2,%3};"
        : "+f"(c[0]), "+f"(c[1]), "+f"(c[2]), "+f"(c[3])
        : "r"(a[0]), "r"(a[1]), "r"(a[2]), "r"(a[3]), "r"(b[0]), "r"(b[1]));
}

__device__ __forceinline__ void cpasync16(uint32_t dst, const void* src) {
    asm volatile("cp.async.cg.shared.global [%0], [%1], 16;\n" :: "r"(dst), "l"(src));
}
__device__ __forceinline__ void cpasync_commit() {
    asm volatile("cp.async.commit_group;\n");
}
template<int N>
__device__ __forceinline__ void cpasync_wait() {
    asm volatile("cp.async.wait_group %0;\n" :: "n"(N));
}

__device__ __forceinline__ float blockReduceSum256(float v) {
    __shared__ float s[8];
    int lane = threadIdx.x & 31, wid = threadIdx.x >> 5;
    #pragma unroll
    for (int o = 16; o; o >>= 1) v += __shfl_xor_sync(0xffffffffu, v, o);
    __syncthreads();
    if (lane == 0) s[wid] = v;
    __syncthreads();
    float r = s[0];
    #pragma unroll
    for (int i = 1; i < 8; i++) r += s[i];
    return r;
}

__device__ __forceinline__ float blockReduceMax256(float v) {
    __shared__ float s[8];
    int lane = threadIdx.x & 31, wid = threadIdx.x >> 5;
    #pragma unroll
    for (int o = 16; o; o >>= 1) v = fmaxf(v, __shfl_xor_sync(0xffffffffu, v, o));
    __syncthreads();
    if (lane == 0) s[wid] = v;
    __syncthreads();
    float r = s[0];
    #pragma unroll
    for (int i = 1; i < 8; i++) r = fmaxf(r, s[i]);
    return r;
}

// ---------------------------------------------------------------------------
// bf16x3 tensor-core GEMM with 3-stage cp.async pipeline.
// C = alpha * A @ B^T (+bias +relu +residual); A ~ Ahi+Alo [M,K], B ~ Bhi+Blo [N,K].
// Batched over grid.z. Outputs fp32 and/or split bf16. BK=32, 256 thr = 8 warps.
// Dynamic smem: STAGES * 2*(BM+BN) * LDS * 2 bytes.
// ---------------------------------------------------------------------------
#define GBK    32
#define GLDS   40            // smem row stride (elems) = GBK + 8 pad
#define GSTG   3             // pipeline stages

template<int BM, int BN, int WM, int WN>
__global__ __launch_bounds__(256) void gemm_bf16x3(
    const bf16* __restrict__ Ahi, const bf16* __restrict__ Alo,
    int lda, long aOffB, long aOffH,
    const bf16* __restrict__ Bhi, const bf16* __restrict__ Blo,
    int ldb, long bOffB, long bOffH,
    float* Cf32, bf16* Chi, bf16* Clo,
    int ldc, long cOffB, long cOffH,
    const float* __restrict__ residual, const float* __restrict__ bias,
    int K, int nH, float alpha, int relu)
{
    constexpr int WARPS_N = BN / WN;
    constexpr int MF  = WM / 16;
    constexpr int NF  = WN / 8;
    constexpr int NG  = WN / 16;
    constexpr int AIT = (BM * GBK) / (8 * 256);
    constexpr int BIT = (BN * GBK) / (8 * 256);
    constexpr int A_STG = BM * GLDS;   // elems per stage per A array
    constexpr int B_STG = BN * GLDS;

    extern __shared__ __align__(16) bf16 smemBuf[];
    bf16* sA_h = smemBuf;
    bf16* sA_l = sA_h + (size_t)GSTG * A_STG;
    bf16* sB_h = sA_l + (size_t)GSTG * A_STG;
    bf16* sB_l = sB_h + (size_t)GSTG * B_STG;

    const int tid  = threadIdx.x;
    const int warp = tid >> 5, lane = tid & 31;
    const int wr = warp / WARPS_N, wc = warp % WARPS_N;
    const int row0 = blockIdx.y * BM;
    const int col0 = blockIdx.x * BN;

    const int z  = blockIdx.z;
    const int zb = z / nH, zh = z % nH;
    const bf16* Ah = Ahi + (long)zb * aOffB + (long)zh * aOffH;
    const bf16* Al = Alo + (long)zb * aOffB + (long)zh * aOffH;
    const bf16* Bh = Bhi + (long)zb * bOffB + (long)zh * bOffH;
    const bf16* Bl = Blo + (long)zb * bOffB + (long)zh * bOffH;
    const long  zC = (long)zb * cOffB + (long)zh * cOffH;

    float acc[MF][NF][4];
    #pragma unroll
    for (int i = 0; i < MF; i++)
        #pragma unroll
        for (int j = 0; j < NF; j++)
            #pragma unroll
            for (int k = 0; k < 4; k++) acc[i][j][k] = 0.f;

    // issue one k-tile's loads into a stage (16B cp.async per slot)
    auto issueTile = [&](int kt) {
        const int stage = kt % GSTG;
        const int k0 = kt * GBK;
        #pragma unroll
        for (int i = 0; i < AIT; i++) {
            int idx = tid + i * 256, r = idx >> 2, c = (idx & 3) * 8;
            uint32_t off = (uint32_t)((stage * BM + r) * GLDS + c);
            cpasync16(smem_u32(sA_h + off), Ah + (long)(row0 + r) * lda + k0 + c);
            cpasync16(smem_u32(sA_l + off), Al + (long)(row0 + r) * lda + k0 + c);
        }
        #pragma unroll
        for (int i = 0; i < BIT; i++) {
            int idx = tid + i * 256, r = idx >> 2, c = (idx & 3) * 8;
            uint32_t off = (uint32_t)((stage * BN + r) * GLDS + c);
            cpasync16(smem_u32(sB_h + off), Bh + (long)(col0 + r) * ldb + k0 + c);
            cpasync16(smem_u32(sB_l + off), Bl + (long)(col0 + r) * ldb + k0 + c);
        }
    };

    const int KT = K / GBK;

    // prologue: stages 0..GSTG-2
    #pragma unroll
    for (int s = 0; s < GSTG - 1; s++) {
        if (s < KT) issueTile(s);
        cpasync_commit();
    }

    // ldmatrix lane addressing (byte offsets within one stage)
    const int aRowL = ((lane >> 3) & 1) * 8 + (lane & 7);
    const int aColL = (lane >> 4) * 8;
    const int bRowL = (lane >> 4) * 8 + (lane & 7);
    const int bColL = ((lane >> 3) & 1) * 8;
    const uint32_t aBaseH0 = smem_u32(sA_h) + ((wr * WM + aRowL) * GLDS + aColL) * 2;
    const uint32_t aBaseL0 = smem_u32(sA_l) + ((wr * WM + aRowL) * GLDS + aColL) * 2;
    const uint32_t bBaseH0 = smem_u32(sB_h) + ((wc * WN + bRowL) * GLDS + bColL) * 2;
    const uint32_t bBaseL0 = smem_u32(sB_l) + ((wc * WN + bRowL) * GLDS + bColL) * 2;

    for (int kt = 0; kt < KT; kt++) {
        if (kt == KT - 1) cpasync_wait<0>();
        else              cpasync_wait<GSTG - 2>();
        __syncthreads();

        // issue-ahead (writes stage (kt-1)%GSTG, safe: all warps passed sync)
        int nk = kt + GSTG - 1;
        if (nk < KT) issueTile(nk);
        cpasync_commit();

        const int stage = kt % GSTG;
        const uint32_t sOffA = (uint32_t)(stage * A_STG * 2);
        const uint32_t sOffB = (uint32_t)(stage * B_STG * 2);

        #pragma unroll
        for (int kk = 0; kk < 2; kk++) {
            const uint32_t koff = kk * 32;  // 16 elems * 2B
            uint32_t aH[MF][4], aL[MF][4];
            #pragma unroll
            for (int mi = 0; mi < MF; mi++) {
                ldsm4(aH[mi], aBaseH0 + sOffA + mi * (16 * GLDS * 2) + koff);
                ldsm4(aL[mi], aBaseL0 + sOffA + mi * (16 * GLDS * 2) + koff);
            }
            uint32_t bH[NF][2], bL[NF][2];
            #pragma unroll
            for (int gi = 0; gi < NG; gi++) {
                uint32_t t4[4];
                ldsm4(t4, bBaseH0 + sOffB + gi * (16 * GLDS * 2) + koff);
                bH[2 * gi][0] = t4[0]; bH[2 * gi][1] = t4[1];
                bH[2 * gi + 1][0] = t4[2]; bH[2 * gi + 1][1] = t4[3];
                ldsm4(t4, bBaseL0 + sOffB + gi * (16 * GLDS * 2) + koff);
                bL[2 * gi][0] = t4[0]; bL[2 * gi][1] = t4[1];
                bL[2 * gi + 1][0] = t4[2]; bL[2 * gi + 1][1] = t4[3];
            }
            #pragma unroll
            for (int mi = 0; mi < MF; mi++)
                #pragma unroll
                for (int nf = 0; nf < NF; nf++) {
                    mma16816(acc[mi][nf], aH[mi], bH[nf]);
                    mma16816(acc[mi][nf], aH[mi], bL[nf]);
                    mma16816(acc[mi][nf], aL[mi], bH[nf]);
                }
        }
    }

    // ---------------- epilogue ----------------
    float*       Cz = Cf32 ? Cf32 + zC : nullptr;
    bf16*        CH = Chi  ? Chi  + zC : nullptr;
    bf16*        CL = Clo  ? Clo  + zC : nullptr;
    const float* Rz = residual ? residual + zC : nullptr;

    #pragma unroll
    for (int mi = 0; mi < MF; mi++)
        #pragma unroll
        for (int nf = 0; nf < NF; nf++) {
            int rbase = row0 + wr * WM + mi * 16 + (lane >> 2);
            int c     = col0 + wc * WN + nf * 8 + (lane & 3) * 2;
            #pragma unroll
            for (int half = 0; half < 2; half++) {
                long r = rbase + half * 8;
                float v0 = acc[mi][nf][half * 2 + 0] * alpha;
                float v1 = acc[mi][nf][half * 2 + 1] * alpha;
                if (bias) { v0 += bias[c]; v1 += bias[c + 1]; }
                if (relu) { v0 = fmaxf(v0, 0.f); v1 = fmaxf(v1, 0.f); }
                if (Rz)   { v0 += Rz[r * (long)ldc + c]; v1 += Rz[r * (long)ldc + c + 1]; }
                if (Cz) {
                    float2 o = make_float2(v0, v1);
                    *(float2*)&Cz[r * (long)ldc + c] = o;
                }
                if (CH) {
                    bf16 h0, l0, h1, l1;
                    split1(v0, h0, l0);
                    split1(v1, h1, l1);
                    *(bf162*)&CH[r * (long)ldc + c] = __halves2bfloat162(h0, h1);
                    *(bf162*)&CL[r * (long)ldc + c] = __halves2bfloat162(l0, l1);
                }
            }
        }
}

// ---------------------------------------------------------------------------
// fp32 -> split bf16 conversion (4 elems/thread)
// ---------------------------------------------------------------------------
__global__ void split4(const float* __restrict__ in, bf16* __restrict__ hi,
                       bf16* __restrict__ lo, size_t n4)
{
    size_t i = (size_t)blockIdx.x * blockDim.x + threadIdx.x;
    if (i >= n4) return;
    float4 v = ((const float4*)in)[i];
    bf16 h0, l0, h1, l1, h2, l2, h3, l3;
    split1(v.x, h0, l0); split1(v.y, h1, l1);
    split1(v.z, h2, l2); split1(v.w, h3, l3);
    ((bf162*)hi)[2 * i + 0] = __halves2bfloat162(h0, h1);
    ((bf162*)hi)[2 * i + 1] = __halves2bfloat162(h2, h3);
    ((bf162*)lo)[2 * i + 0] = __halves2bfloat162(l0, l1);
    ((bf162*)lo)[2 * i + 1] = __halves2bfloat162(l2, l3);
}

// ---------------------------------------------------------------------------
// V [b,s,(h,d)] fp32 -> Vt [(b,h), d, s] split bf16
// ---------------------------------------------------------------------------
__global__ void transpose_split_v(const float* __restrict__ V,
                                  bf16* __restrict__ Vth, bf16* __restrict__ Vtl)
{
    __shared__ float t[32][33];
    int z = blockIdx.z, b = z >> 4, h = z & 15;
    int s0 = blockIdx.x * 32, d0 = blockIdx.y * 32;
    #pragma unroll
    for (int j = 0; j < 4; j++) {
        int s = s0 + threadIdx.y + j * 8;
        t[threadIdx.y + j * 8][threadIdx.x] =
            V[(size_t)(b * S_LEN + s) * E_DIM + h * HD_DIM + d0 + threadIdx.x];
    }
    __syncthreads();
    #pragma unroll
    for (int j = 0; j < 4; j++) {
        int d = d0 + threadIdx.y + j * 8;
        float v = t[threadIdx.x][threadIdx.y + j * 8];
        bf16 hh, ll;
        split1(v, hh, ll);
        size_t o = ((size_t)z * HD_DIM + d) * S_LEN + s0 + threadIdx.x;
        Vth[o] = hh;
        Vtl[o] = ll;
    }
}

// ---------------------------------------------------------------------------
// Softmax rows (S=2048). Reads fp32 row, writes split bf16 IN PLACE:
// hi at row*4096 (bf16 elems), lo at row*4096+2048.
// ---------------------------------------------------------------------------
__global__ __launch_bounds__(256) void softmax_split_inplace(float* __restrict__ P)
{
    size_t row = blockIdx.x;
    const float4* p4 = (const float4*)(P + row * (size_t)S_LEN);
    int tid = threadIdx.x;

    float4 v0 = p4[2 * tid], v1 = p4[2 * tid + 1];
    float m = fmaxf(fmaxf(fmaxf(v0.x, v0.y), fmaxf(v0.z, v0.w)),
                    fmaxf(fmaxf(v1.x, v1.y), fmaxf(v1.z, v1.w)));
    m = blockReduceMax256(m);   // __syncthreads inside: reads done before writes

    v0.x = __expf(v0.x - m); v0.y = __expf(v0.y - m);
    v0.z = __expf(v0.z - m); v0.w = __expf(v0.w - m);
    v1.x = __expf(v1.x - m); v1.y = __expf(v1.y - m);
    v1.z = __expf(v1.z - m); v1.w = __expf(v1.w - m);

    float s = (v0.x + v0.y + v0.z + v0.w) + (v1.x + v1.y + v1.z + v1.w);
    s = blockReduceSum256(s);
    float inv = 1.f / s;

    float vals[8] = {v0.x * inv, v0.y * inv, v0.z * inv, v0.w * inv,
                     v1.x * inv, v1.y * inv, v1.z * inv, v1.w * inv};

    bf16* rowb = (bf16*)P + row * (size_t)(2 * S_LEN);
    bf162* ph2 = (bf162*)rowb;
    bf162* pl2 = (bf162*)(rowb + S_LEN);
    #pragma unroll
    for (int j = 0; j < 4; j++) {
        bf16 h0, l0, h1, l1;
        split1(vals[2 * j], h0, l0);
        split1(vals[2 * j + 1], h1, l1);
        ph2[4 * tid + j] = __halves2bfloat162(h0, h1);
        pl2[4 * tid + j] = __halves2bfloat162(l0, l1);
    }
}

// ---------------------------------------------------------------------------
// LayerNorm (E=1024), fp32 out + optional split bf16 out
// ---------------------------------------------------------------------------
__global__ __launch_bounds__(256) void layernorm_rows(
    const float* __restrict__ in,
    const float* __restrict__ g, const float* __restrict__ b,
    float* __restrict__ out, bf16* __restrict__ ohi, bf16* __restrict__ olo)
{
    size_t row = blockIdx.x;
    const float4* x4 = (const float4*)(in + row * E_DIM);
    float4 v = x4[threadIdx.x];

    float s  = v.x + v.y + v.z + v.w;
    float ss = v.x * v.x + v.y * v.y + v.z * v.z + v.w * v.w;
    s  = blockReduceSum256(s);
    ss = blockReduceSum256(ss);

    const float invE = 1.f / (float)E_DIM;
    float mu   = s * invE;
    float var  = ss * invE - mu * mu;
    float rstd = rsqrtf(var + LN_EPS);

    float4 gv = ((const float4*)g)[threadIdx.x];
    float4 bv = ((const float4*)b)[threadIdx.x];
    float4 o;
    o.x = (v.x - mu) * rstd * gv.x + bv.x;
    o.y = (v.y - mu) * rstd * gv.y + bv.y;
    o.z = (v.z - mu) * rstd * gv.z + bv.z;
    o.w = (v.w - mu) * rstd * gv.w + bv.w;
    ((float4*)(out + row * E_DIM))[threadIdx.x] = o;

    if (ohi) {
        bf16 h0, l0, h1, l1, h2, l2, h3, l3;
        split1(o.x, h0, l0); split1(o.y, h1, l1);
        split1(o.z, h2, l2); split1(o.w, h3, l3);
        bf162* ph = (bf162*)(ohi + row * E_DIM);
        bf162* pl = (bf162*)(olo + row * E_DIM);
        ph[2 * threadIdx.x + 0] = __halves2bfloat162(h0, h1);
        ph[2 * threadIdx.x + 1] = __halves2bfloat162(h2, h3);
        pl[2 * threadIdx.x + 0] = __halves2bfloat162(l0, l1);
        pl[2 * threadIdx.x + 1] = __halves2bfloat162(l2, l3);
    }
}

// ---------------------------------------------------------------------------
// Launch
// Inputs: 0:x 1:Wq 2:Wk 3:Wv 4:Wo 5:g1 6:b1 7:g2 8:b2 9:W1 10:bb1 11:W2 12:bb2
// ---------------------------------------------------------------------------
#define SYMADDR(v, s) cudaGetSymbolAddress((void**)&v, s)

// dynamic smem: GSTG * 2*(BM+BN) * GLDS * 2 bytes
#define GEMM_SMEM(BM, BN) (GSTG * 2 * ((BM) + (BN)) * GLDS * 2)

extern "C" void kernel_launch(void* const* d_in, const int* in_sizes, int n_in,
                              void* d_out, int out_size)
{
    const float* x   = (const float*)d_in[0];
    const float* Wq  = (const float*)d_in[1];
    const float* Wk  = (const float*)d_in[2];
    const float* Wv  = (const float*)d_in[3];
    const float* Wo  = (const float*)d_in[4];
    const float* g1  = (const float*)d_in[5];
    const float* b1  = (const float*)d_in[6];
    const float* g2  = (const float*)d_in[7];
    const float* b2  = (const float*)d_in[8];
    const float* W1  = (const float*)d_in[9];
    const float* bb1 = (const float*)d_in[10];
    const float* W2  = (const float*)d_in[11];
    const float* bb2 = (const float*)d_in[12];
    float* out = (float*)d_out;

    float *P, *res1, *h, *res2;
    bf16 *xh, *xl, *Wqh, *Wql, *Wkh, *Wkl, *Wvh, *Wvl, *Woh, *Wol;
    bf16 *W1h, *W1l, *W2h, *W2l, *Qh, *Ql, *Kh, *Kl, *Vth, *Vtl;
    bf16 *ah, *al, *hh, *hl, *fh, *fl;
    SYMADDR(P, g_P); SYMADDR(res1, g_res1);
    SYMADDR(h, g_h); SYMADDR(res2, g_res2);
    SYMADDR(xh, g_xh); SYMADDR(xl, g_xl);
    SYMADDR(Wqh, g_Wqh); SYMADDR(Wql, g_Wql);
    SYMADDR(Wkh, g_Wkh); SYMADDR(Wkl, g_Wkl);
    SYMADDR(Wvh, g_Wvh); SYMADDR(Wvl, g_Wvl);
    SYMADDR(Woh, g_Woh); SYMADDR(Wol, g_Wol);
    SYMADDR(W1h, g_W1h); SYMADDR(W1l, g_W1l);
    SYMADDR(W2h, g_W2h); SYMADDR(W2l, g_W2l);
    SYMADDR(Qh, g_Qh); SYMADDR(Ql, g_Ql);
    SYMADDR(Kh, g_Kh); SYMADDR(Kl, g_Kl);
    SYMADDR(Vth, g_Vth); SYMADDR(Vtl, g_Vtl);
    SYMADDR(ah, g_ah); SYMADDR(al, g_al);
    SYMADDR(hh, g_hh); SYMADDR(hl, g_hl);
    SYMADDR(fh, g_fh); SYMADDR(fl, g_fl);

    float* Vf32 = res1;                 // V projection parks in res1 (free here)
    bf16*  Pb16 = (bf16*)P;             // after softmax: hi/lo interleaved rows

    const int SM_BIG = GEMM_SMEM(128, 128);   // 122880
    const int SM_PV  = GEMM_SMEM(128, 64);    //  92160
    cudaFuncSetAttribute(gemm_bf16x3<128,128,64,32>,
                         cudaFuncAttributeMaxDynamicSharedMemorySize, SM_BIG);
    cudaFuncSetAttribute(gemm_bf16x3<128,64,32,32>,
                         cudaFuncAttributeMaxDynamicSharedMemorySize, SM_PV);

    dim3 blk(256);

    // --- split inputs/weights ---
    auto splitLaunch = [&](const float* src, bf16* hi, bf16* lo, size_t n) {
        size_t n4 = n / 4;
        split4<<<(unsigned)((n4 + 255) / 256), 256>>>(src, hi, lo, n4);
    };
    splitLaunch(x,  xh,  xl,  (size_t)N_TOK * E_DIM);
    splitLaunch(Wq, Wqh, Wql, (size_t)E_DIM * E_DIM);
    splitLaunch(Wk, Wkh, Wkl, (size_t)E_DIM * E_DIM);
    splitLaunch(Wv, Wvh, Wvl, (size_t)E_DIM * E_DIM);
    splitLaunch(Wo, Woh, Wol, (size_t)E_DIM * E_DIM);
    splitLaunch(W1, W1h, W1l, (size_t)F_DIM * E_DIM);
    splitLaunch(W2, W2h, W2l, (size_t)E_DIM * F_DIM);

    // --- QKV projections ---
    dim3 gp(E_DIM / 128, N_TOK / 128, 1);
    gemm_bf16x3<128,128,64,32><<<gp, blk, SM_BIG>>>(
        xh, xl, E_DIM, 0, 0,  Wqh, Wql, E_DIM, 0, 0,
        nullptr, Qh, Ql, E_DIM, 0, 0,
        nullptr, nullptr, E_DIM, 1, 1.f, 0);
    gemm_bf16x3<128,128,64,32><<<gp, blk, SM_BIG>>>(
        xh, xl, E_DIM, 0, 0,  Wkh, Wkl, E_DIM, 0, 0,
        nullptr, Kh, Kl, E_DIM, 0, 0,
        nullptr, nullptr, E_DIM, 1, 1.f, 0);
    gemm_bf16x3<128,128,64,32><<<gp, blk, SM_BIG>>>(
        xh, xl, E_DIM, 0, 0,  Wvh, Wvl, E_DIM, 0, 0,
        Vf32, nullptr, nullptr, E_DIM, 0, 0,
        nullptr, nullptr, E_DIM, 1, 1.f, 0);

    // --- V transpose + split ---
    transpose_split_v<<<dim3(S_LEN / 32, HD_DIM / 32, BH_NUM), dim3(32, 8)>>>(Vf32, Vth, Vtl);

    // --- scores = QK^T / 8 ---
    dim3 gs(S_LEN / 128, S_LEN / 128, BH_NUM);
    gemm_bf16x3<128,128,64,32><<<gs, blk, SM_BIG>>>(
        Qh, Ql, E_DIM, (long)S_LEN * E_DIM, HD_DIM,
        Kh, Kl, E_DIM, (long)S_LEN * E_DIM, HD_DIM,
        P, nullptr, nullptr, S_LEN, (long)H_NUM * S_LEN * S_LEN, (long)S_LEN * S_LEN,
        nullptr, nullptr, HD_DIM, H_NUM, 0.125f, 0);

    // --- softmax -> split probs in place (row stride 4096 bf16) ---
    softmax_split_inplace<<<BH_NUM * S_LEN, 256>>>(P);

    // --- attn = P @ V (via Vt), written to [b,s,(h,d)] split ---
    dim3 gpv(1, S_LEN / 128, BH_NUM);
    gemm_bf16x3<128,64,32,32><<<gpv, blk, SM_PV>>>(
        Pb16, Pb16 + S_LEN,                       // hi rows / lo rows
        2 * S_LEN,                                // lda = 4096 bf16
        (long)H_NUM * S_LEN * 2 * S_LEN, (long)S_LEN * 2 * S_LEN,
        Vth, Vtl, S_LEN, (long)H_NUM * HD_DIM * S_LEN, (long)HD_DIM * S_LEN,
        nullptr, ah, al, E_DIM, (long)S_LEN * E_DIM, HD_DIM,
        nullptr, nullptr, S_LEN, H_NUM, 1.f, 0);

    // --- O projection + residual x ---
    gemm_bf16x3<128,128,64,32><<<gp, blk, SM_BIG>>>(
        ah, al, E_DIM, 0, 0,  Woh, Wol, E_DIM, 0, 0,
        res1, nullptr, nullptr, E_DIM, 0, 0,
        x, nullptr, E_DIM, 1, 1.f, 0);

    // --- LN1 -> h (fp32 + split) ---
    layernorm_rows<<<N_TOK, 256>>>(res1, g1, b1, h, hh, hl);

    // --- FFN1: relu(h @ W1^T + bb1) -> split ---
    dim3 gf1(F_DIM / 128, N_TOK / 128, 1);
    gemm_bf16x3<128,128,64,32><<<gf1, blk, SM_BIG>>>(
        hh, hl, E_DIM, 0, 0,  W1h, W1l, E_DIM, 0, 0,
        nullptr, fh, fl, F_DIM, 0, 0,
        nullptr, bb1, E_DIM, 1, 1.f, 1);

    // --- FFN2: ffn @ W2^T + bb2 + h ---
    gemm_bf16x3<128,128,64,32><<<gp, blk, SM_BIG>>>(
        fh, fl, F_DIM, 0, 0,  W2h, W2l, F_DIM, 0, 0,
        res2, nullptr, nullptr, E_DIM, 0, 0,
        h, bb2, F_DIM, 1, 1.f, 0);

    // --- LN2 -> out ---
    layernorm_rows<<<N_TOK, 256>>>(res2, g2, b2, out, nullptr, nullptr);
}

// round 10
// speedup vs baseline: 2.4643x; 2.4643x over previous
#include <cuda_runtime.h>
#include <cuda_fp16.h>
#include <math.h>
#include <stdint.h>

typedef __half  f16;
typedef __half2 f162;

// ---------------------------------------------------------------------------
// Problem constants
// ---------------------------------------------------------------------------
#define E_DIM   1024
#define H_NUM   16
#define HD_DIM  64
#define F_DIM   4096
#define B_NUM   4
#define S_LEN   2048
#define N_TOK   (B_NUM * S_LEN)      // 8192
#define BH_NUM  (B_NUM * H_NUM)      // 64
#define LN_EPS  1e-5f

// ---------------------------------------------------------------------------
// Scratch buffers (static device globals) — total ~1.26 GB
// ---------------------------------------------------------------------------
__device__ float g_P   [(size_t)BH_NUM * S_LEN * S_LEN];   // 1 GB; post-softmax
                                                           // holds fp16 rows
__device__ float g_res1[(size_t)N_TOK * E_DIM];            // 32 MB (also V fp32)
__device__ float g_h   [(size_t)N_TOK * E_DIM];
__device__ float g_res2[(size_t)N_TOK * E_DIM];
__device__ f16 g_xh [(size_t)N_TOK * E_DIM];
__device__ f16 g_Wqh[(size_t)E_DIM * E_DIM];
__device__ f16 g_Wkh[(size_t)E_DIM * E_DIM];
__device__ f16 g_Wvh[(size_t)E_DIM * E_DIM];
__device__ f16 g_Woh[(size_t)E_DIM * E_DIM];
__device__ f16 g_W1h[(size_t)F_DIM * E_DIM];
__device__ f16 g_W2h[(size_t)E_DIM * F_DIM];
__device__ f16 g_Qh [(size_t)N_TOK * E_DIM];
__device__ f16 g_Kh [(size_t)N_TOK * E_DIM];
__device__ f16 g_Vth[(size_t)BH_NUM * HD_DIM * S_LEN];
__device__ f16 g_ah [(size_t)N_TOK * E_DIM];
__device__ f16 g_hh [(size_t)N_TOK * E_DIM];
__device__ f16 g_fh [(size_t)N_TOK * F_DIM];

// ---------------------------------------------------------------------------
// Helpers
// ---------------------------------------------------------------------------
__device__ __forceinline__ uint32_t smem_u32(const void* p) {
    return (uint32_t)__cvta_generic_to_shared(p);
}

__device__ __forceinline__ void ldsm4(uint32_t* r, uint32_t a) {
    asm volatile("ldmatrix.sync.aligned.m8n8.x4.shared.b16 {%0,%1,%2,%3}, [%4];"
        : "=r"(r[0]), "=r"(r[1]), "=r"(r[2]), "=r"(r[3]) : "r"(a));
}

__device__ __forceinline__ void mma16816(float* c, const uint32_t* a, const uint32_t* b) {
    asm volatile(
        "mma.sync.aligned.m16n8k16.row.col.f32.f16.f16.f32 "
        "{%0,%1,%2,%3}, {%4,%5,%6,%7}, {%8,%9}, {%0,%1,%2,%3};"
        : "+f"(c[0]), "+f"(c[1]), "+f"(c[2]), "+f"(c[3])
        : "r"(a[0]), "r"(a[1]), "r"(a[2]), "r"(a[3]), "r"(b[0]), "r"(b[1]));
}

__device__ __forceinline__ void cpasync16(uint32_t dst, const void* src) {
    asm volatile("cp.async.cg.shared.global [%0], [%1], 16;\n" :: "r"(dst), "l"(src));
}
__device__ __forceinline__ void cpasync_commit() {
    asm volatile("cp.async.commit_group;\n");
}
template<int N>
__device__ __forceinline__ void cpasync_wait() {
    asm volatile("cp.async.wait_group %0;\n" :: "n"(N));
}

__device__ __forceinline__ float blockReduceSum256(float v) {
    __shared__ float s[8];
    int lane = threadIdx.x & 31, wid = threadIdx.x >> 5;
    #pragma unroll
    for (int o = 16; o; o >>= 1) v += __shfl_xor_sync(0xffffffffu, v, o);
    __syncthreads();
    if (lane == 0) s[wid] = v;
    __syncthreads();
    float r = s[0];
    #pragma unroll
    for (int i = 1; i < 8; i++) r += s[i];
    return r;
}

__device__ __forceinline__ float blockReduceMax256(float v) {
    __shared__ float s[8];
    int lane = threadIdx.x & 31, wid = threadIdx.x >> 5;
    #pragma unroll
    for (int o = 16; o; o >>= 1) v = fmaxf(v, __shfl_xor_sync(0xffffffffu, v, o));
    __syncthreads();
    if (lane == 0) s[wid] = v;
    __syncthreads();
    float r = s[0];
    #pragma unroll
    for (int i = 1; i < 8; i++) r = fmaxf(r, s[i]);
    return r;
}

// ---------------------------------------------------------------------------
// fp16 tensor-core GEMM with 3-stage cp.async pipeline.
// C = alpha * A @ B^T (+bias +relu +residual); A [M,K], B [N,K] fp16 row-major.
// fp32 accumulate. Batched over grid.z. BK=32, 256 thr = 8 warps.
// ---------------------------------------------------------------------------
#define GBK    32
#define GLDS   40            // smem row stride (elems) = GBK + 8 pad
#define GSTG   3             // pipeline stages

template<int BM, int BN, int WM, int WN>
__global__ __launch_bounds__(256, 2) void gemm_fp16(
    const f16* __restrict__ A, int lda, long aOffB, long aOffH,
    const f16* __restrict__ B, int ldb, long bOffB, long bOffH,
    float* Cf32, f16* Ch,
    int ldc, long cOffB, long cOffH,
    const float* __restrict__ residual, const float* __restrict__ bias,
    int K, int nH, float alpha, int relu)
{
    constexpr int WARPS_N = BN / WN;
    constexpr int MF  = WM / 16;
    constexpr int NF  = WN / 8;
    constexpr int NG  = WN / 16;
    constexpr int AIT = (BM * GBK) / (8 * 256);
    constexpr int BIT = (BN * GBK) / (8 * 256);
    constexpr int A_STG = BM * GLDS;
    constexpr int B_STG = BN * GLDS;

    extern __shared__ __align__(16) f16 smemBuf[];
    f16* sA = smemBuf;
    f16* sB = sA + (size_t)GSTG * A_STG;

    const int tid  = threadIdx.x;
    const int warp = tid >> 5, lane = tid & 31;
    const int wr = warp / WARPS_N, wc = warp % WARPS_N;
    const int row0 = blockIdx.y * BM;
    const int col0 = blockIdx.x * BN;

    const int z  = blockIdx.z;
    const int zb = z / nH, zh = z % nH;
    const f16* Az = A + (long)zb * aOffB + (long)zh * aOffH;
    const f16* Bz = B + (long)zb * bOffB + (long)zh * bOffH;
    const long  zC = (long)zb * cOffB + (long)zh * cOffH;

    float acc[MF][NF][4];
    #pragma unroll
    for (int i = 0; i < MF; i++)
        #pragma unroll
        for (int j = 0; j < NF; j++)
            #pragma unroll
            for (int k = 0; k < 4; k++) acc[i][j][k] = 0.f;

    auto issueTile = [&](int kt) {
        const int stage = kt % GSTG;
        const int k0 = kt * GBK;
        #pragma unroll
        for (int i = 0; i < AIT; i++) {
            int idx = tid + i * 256, r = idx >> 2, c = (idx & 3) * 8;
            cpasync16(smem_u32(sA + (uint32_t)((stage * BM + r) * GLDS + c)),
                      Az + (long)(row0 + r) * lda + k0 + c);
        }
        #pragma unroll
        for (int i = 0; i < BIT; i++) {
            int idx = tid + i * 256, r = idx >> 2, c = (idx & 3) * 8;
            cpasync16(smem_u32(sB + (uint32_t)((stage * BN + r) * GLDS + c)),
                      Bz + (long)(col0 + r) * ldb + k0 + c);
        }
    };

    const int KT = K / GBK;

    #pragma unroll
    for (int s = 0; s < GSTG - 1; s++) {
        if (s < KT) issueTile(s);
        cpasync_commit();
    }

    const int aRowL = ((lane >> 3) & 1) * 8 + (lane & 7);
    const int aColL = (lane >> 4) * 8;
    const int bRowL = (lane >> 4) * 8 + (lane & 7);
    const int bColL = ((lane >> 3) & 1) * 8;
    const uint32_t aBase0 = smem_u32(sA) + ((wr * WM + aRowL) * GLDS + aColL) * 2;
    const uint32_t bBase0 = smem_u32(sB) + ((wc * WN + bRowL) * GLDS + bColL) * 2;

    for (int kt = 0; kt < KT; kt++) {
        if (kt == KT - 1) cpasync_wait<0>();
        else              cpasync_wait<GSTG - 2>();
        __syncthreads();

        int nk = kt + GSTG - 1;
        if (nk < KT) issueTile(nk);
        cpasync_commit();

        const int stage = kt % GSTG;
        const uint32_t sOffA = (uint32_t)(stage * A_STG * 2);
        const uint32_t sOffB = (uint32_t)(stage * B_STG * 2);

        #pragma unroll
        for (int kk = 0; kk < 2; kk++) {
            const uint32_t koff = kk * 32;  // 16 elems * 2B
            uint32_t aR[MF][4];
            #pragma unroll
            for (int mi = 0; mi < MF; mi++)
                ldsm4(aR[mi], aBase0 + sOffA + mi * (16 * GLDS * 2) + koff);
            uint32_t bR[NF][2];
            #pragma unroll
            for (int gi = 0; gi < NG; gi++) {
                uint32_t t4[4];
                ldsm4(t4, bBase0 + sOffB + gi * (16 * GLDS * 2) + koff);
                bR[2 * gi][0] = t4[0]; bR[2 * gi][1] = t4[1];
                bR[2 * gi + 1][0] = t4[2]; bR[2 * gi + 1][1] = t4[3];
            }
            #pragma unroll
            for (int mi = 0; mi < MF; mi++)
                #pragma unroll
                for (int nf = 0; nf < NF; nf++)
                    mma16816(acc[mi][nf], aR[mi], bR[nf]);
        }
    }

    // ---------------- epilogue ----------------
    float*       Cz = Cf32 ? Cf32 + zC : nullptr;
    f16*         CH = Ch   ? Ch   + zC : nullptr;
    const float* Rz = residual ? residual + zC : nullptr;

    #pragma unroll
    for (int mi = 0; mi < MF; mi++)
        #pragma unroll
        for (int nf = 0; nf < NF; nf++) {
            int rbase = row0 + wr * WM + mi * 16 + (lane >> 2);
            int c     = col0 + wc * WN + nf * 8 + (lane & 3) * 2;
            #pragma unroll
            for (int half = 0; half < 2; half++) {
                long r = rbase + half * 8;
                float v0 = acc[mi][nf][half * 2 + 0] * alpha;
                float v1 = acc[mi][nf][half * 2 + 1] * alpha;
                if (bias) { v0 += bias[c]; v1 += bias[c + 1]; }
                if (relu) { v0 = fmaxf(v0, 0.f); v1 = fmaxf(v1, 0.f); }
                if (Rz)   { v0 += Rz[r * (long)ldc + c]; v1 += Rz[r * (long)ldc + c + 1]; }
                if (Cz) *(float2*)&Cz[r * (long)ldc + c] = make_float2(v0, v1);
                if (CH) *(f162*)&CH[r * (long)ldc + c] =
                            __floats2half2_rn(v0, v1);
            }
        }
}

// ---------------------------------------------------------------------------
// fp32 -> fp16 conversion (4 elems/thread)
// ---------------------------------------------------------------------------
__global__ void cvt4(const float* __restrict__ in, f16* __restrict__ out, size_t n4)
{
    size_t i = (size_t)blockIdx.x * blockDim.x + threadIdx.x;
    if (i >= n4) return;
    float4 v = ((const float4*)in)[i];
    ((f162*)out)[2 * i + 0] = __floats2half2_rn(v.x, v.y);
    ((f162*)out)[2 * i + 1] = __floats2half2_rn(v.z, v.w);
}

// ---------------------------------------------------------------------------
// V [b,s,(h,d)] fp32 -> Vt [(b,h), d, s] fp16
// ---------------------------------------------------------------------------
__global__ void transpose_cvt_v(const float* __restrict__ V, f16* __restrict__ Vt)
{
    __shared__ float t[32][33];
    int z = blockIdx.z, b = z >> 4, h = z & 15;
    int s0 = blockIdx.x * 32, d0 = blockIdx.y * 32;
    #pragma unroll
    for (int j = 0; j < 4; j++) {
        int s = s0 + threadIdx.y + j * 8;
        t[threadIdx.y + j * 8][threadIdx.x] =
            V[(size_t)(b * S_LEN + s) * E_DIM + h * HD_DIM + d0 + threadIdx.x];
    }
    __syncthreads();
    #pragma unroll
    for (int j = 0; j < 4; j++) {
        int d = d0 + threadIdx.y + j * 8;
        Vt[((size_t)z * HD_DIM + d) * S_LEN + s0 + threadIdx.x] =
            __float2half_rn(t[threadIdx.x][threadIdx.y + j * 8]);
    }
}

// ---------------------------------------------------------------------------
// Softmax rows (S=2048). Reads fp32 row, writes fp16 IN PLACE into the first
// half of the same 8KB row (fp16 row stride = 2*S_LEN elems).
// ---------------------------------------------------------------------------
__global__ __launch_bounds__(256) void softmax_cvt_inplace(float* __restrict__ P)
{
    size_t row = blockIdx.x;
    const float4* p4 = (const float4*)(P + row * (size_t)S_LEN);
    int tid = threadIdx.x;

    float4 v0 = p4[2 * tid], v1 = p4[2 * tid + 1];
    float m = fmaxf(fmaxf(fmaxf(v0.x, v0.y), fmaxf(v0.z, v0.w)),
                    fmaxf(fmaxf(v1.x, v1.y), fmaxf(v1.z, v1.w)));
    m = blockReduceMax256(m);   // __syncthreads inside: reads done before writes

    v0.x = __expf(v0.x - m); v0.y = __expf(v0.y - m);
    v0.z = __expf(v0.z - m); v0.w = __expf(v0.w - m);
    v1.x = __expf(v1.x - m); v1.y = __expf(v1.y - m);
    v1.z = __expf(v1.z - m); v1.w = __expf(v1.w - m);

    float s = (v0.x + v0.y + v0.z + v0.w) + (v1.x + v1.y + v1.z + v1.w);
    s = blockReduceSum256(s);
    float inv = 1.f / s;

    f162* ph2 = (f162*)((f16*)P + row * (size_t)(2 * S_LEN));
    ph2[4 * tid + 0] = __floats2half2_rn(v0.x * inv, v0.y * inv);
    ph2[4 * tid + 1] = __floats2half2_rn(v0.z * inv, v0.w * inv);
    ph2[4 * tid + 2] = __floats2half2_rn(v1.x * inv, v1.y * inv);
    ph2[4 * tid + 3] = __floats2half2_rn(v1.z * inv, v1.w * inv);
}

// ---------------------------------------------------------------------------
// LayerNorm (E=1024), fp32 out + optional fp16 out
// ---------------------------------------------------------------------------
__global__ __launch_bounds__(256) void layernorm_rows(
    const float* __restrict__ in,
    const float* __restrict__ g, const float* __restrict__ b,
    float* __restrict__ out, f16* __restrict__ oh)
{
    size_t row = blockIdx.x;
    const float4* x4 = (const float4*)(in + row * E_DIM);
    float4 v = x4[threadIdx.x];

    float s  = v.x + v.y + v.z + v.w;
    float ss = v.x * v.x + v.y * v.y + v.z * v.z + v.w * v.w;
    s  = blockReduceSum256(s);
    ss = blockReduceSum256(ss);

    const float invE = 1.f / (float)E_DIM;
    float mu   = s * invE;
    float var  = ss * invE - mu * mu;
    float rstd = rsqrtf(var + LN_EPS);

    float4 gv = ((const float4*)g)[threadIdx.x];
    float4 bv = ((const float4*)b)[threadIdx.x];
    float4 o;
    o.x = (v.x - mu) * rstd * gv.x + bv.x;
    o.y = (v.y - mu) * rstd * gv.y + bv.y;
    o.z = (v.z - mu) * rstd * gv.z + bv.z;
    o.w = (v.w - mu) * rstd * gv.w + bv.w;
    ((float4*)(out + row * E_DIM))[threadIdx.x] = o;

    if (oh) {
        f162* ph = (f162*)(oh + row * E_DIM);
        ph[2 * threadIdx.x + 0] = __floats2half2_rn(o.x, o.y);
        ph[2 * threadIdx.x + 1] = __floats2half2_rn(o.z, o.w);
    }
}

// ---------------------------------------------------------------------------
// Launch
// Inputs: 0:x 1:Wq 2:Wk 3:Wv 4:Wo 5:g1 6:b1 7:g2 8:b2 9:W1 10:bb1 11:W2 12:bb2
// ---------------------------------------------------------------------------
#define SYMADDR(v, s) cudaGetSymbolAddress((void**)&v, s)

// dynamic smem bytes: GSTG * (BM + BN) * GLDS * 2
#define GEMM_SMEM(BM, BN) (GSTG * ((BM) + (BN)) * GLDS * 2)

extern "C" void kernel_launch(void* const* d_in, const int* in_sizes, int n_in,
                              void* d_out, int out_size)
{
    const float* x   = (const float*)d_in[0];
    const float* Wq  = (const float*)d_in[1];
    const float* Wk  = (const float*)d_in[2];
    const float* Wv  = (const float*)d_in[3];
    const float* Wo  = (const float*)d_in[4];
    const float* g1  = (const float*)d_in[5];
    const float* b1  = (const float*)d_in[6];
    const float* g2  = (const float*)d_in[7];
    const float* b2  = (const float*)d_in[8];
    const float* W1  = (const float*)d_in[9];
    const float* bb1 = (const float*)d_in[10];
    const float* W2  = (const float*)d_in[11];
    const float* bb2 = (const float*)d_in[12];
    float* out = (float*)d_out;

    float *P, *res1, *h, *res2;
    f16 *xh, *Wqh, *Wkh, *Wvh, *Woh, *W1h, *W2h;
    f16 *Qh, *Kh, *Vth, *ah, *hh, *fh;
    SYMADDR(P, g_P); SYMADDR(res1, g_res1);
    SYMADDR(h, g_h); SYMADDR(res2, g_res2);
    SYMADDR(xh, g_xh);
    SYMADDR(Wqh, g_Wqh); SYMADDR(Wkh, g_Wkh);
    SYMADDR(Wvh, g_Wvh); SYMADDR(Woh, g_Woh);
    SYMADDR(W1h, g_W1h); SYMADDR(W2h, g_W2h);
    SYMADDR(Qh, g_Qh); SYMADDR(Kh, g_Kh);
    SYMADDR(Vth, g_Vth);
    SYMADDR(ah, g_ah); SYMADDR(hh, g_hh); SYMADDR(fh, g_fh);

    float* Vf32 = res1;                 // V projection parks in res1 (free here)
    f16*   Pf16 = (f16*)P;              // after softmax: fp16 rows, stride 2*S_LEN

    const int SM_128 = GEMM_SMEM(128, 128);   // 61440
    const int SM_PV  = GEMM_SMEM(128, 64);    // 46080
    cudaFuncSetAttribute(gemm_fp16<128,128,64,32>,
                         cudaFuncAttributeMaxDynamicSharedMemorySize, SM_128);
    cudaFuncSetAttribute(gemm_fp16<128,64,32,32>,
                         cudaFuncAttributeMaxDynamicSharedMemorySize, SM_PV);

    dim3 blk(256);

    // --- convert inputs/weights to fp16 ---
    auto cvtLaunch = [&](const float* src, f16* dst, size_t n) {
        size_t n4 = n / 4;
        cvt4<<<(unsigned)((n4 + 255) / 256), 256>>>(src, dst, n4);
    };
    cvtLaunch(x,  xh,  (size_t)N_TOK * E_DIM);
    cvtLaunch(Wq, Wqh, (size_t)E_DIM * E_DIM);
    cvtLaunch(Wk, Wkh, (size_t)E_DIM * E_DIM);
    cvtLaunch(Wv, Wvh, (size_t)E_DIM * E_DIM);
    cvtLaunch(Wo, Woh, (size_t)E_DIM * E_DIM);
    cvtLaunch(W1, W1h, (size_t)F_DIM * E_DIM);
    cvtLaunch(W2, W2h, (size_t)E_DIM * F_DIM);

    // --- QKV projections ---
    dim3 gp(E_DIM / 128, N_TOK / 128, 1);
    gemm_fp16<128,128,64,32><<<gp, blk, SM_128>>>(
        xh, E_DIM, 0, 0,  Wqh, E_DIM, 0, 0,
        nullptr, Qh, E_DIM, 0, 0,
        nullptr, nullptr, E_DIM, 1, 1.f, 0);
    gemm_fp16<128,128,64,32><<<gp, blk, SM_128>>>(
        xh, E_DIM, 0, 0,  Wkh, E_DIM, 0, 0,
        nullptr, Kh, E_DIM, 0, 0,
        nullptr, nullptr, E_DIM, 1, 1.f, 0);
    gemm_fp16<128,128,64,32><<<gp, blk, SM_128>>>(
        xh, E_DIM, 0, 0,  Wvh, E_DIM, 0, 0,
        Vf32, nullptr, E_DIM, 0, 0,
        nullptr, nullptr, E_DIM, 1, 1.f, 0);

    // --- V transpose + convert ---
    transpose_cvt_v<<<dim3(S_LEN / 32, HD_DIM / 32, BH_NUM), dim3(32, 8)>>>(Vf32, Vth);

    // --- scores = QK^T / 8 ---
    dim3 gs(S_LEN / 128, S_LEN / 128, BH_NUM);
    gemm_fp16<128,128,64,32><<<gs, blk, SM_128>>>(
        Qh, E_DIM, (long)S_LEN * E_DIM, HD_DIM,
        Kh, E_DIM, (long)S_LEN * E_DIM, HD_DIM,
        P, nullptr, S_LEN, (long)H_NUM * S_LEN * S_LEN, (long)S_LEN * S_LEN,
        nullptr, nullptr, HD_DIM, H_NUM, 0.125f, 0);

    // --- softmax -> fp16 probs in place (row stride 2*S_LEN fp16) ---
    softmax_cvt_inplace<<<BH_NUM * S_LEN, 256>>>(P);

    // --- attn = P @ V (via Vt), written to [b,s,(h,d)] fp16 ---
    dim3 gpv(1, S_LEN / 128, BH_NUM);
    gemm_fp16<128,64,32,32><<<gpv, blk, SM_PV>>>(
        Pf16, 2 * S_LEN,
        (long)H_NUM * S_LEN * 2 * S_LEN, (long)S_LEN * 2 * S_LEN,
        Vth, S_LEN, (long)H_NUM * HD_DIM * S_LEN, (long)HD_DIM * S_LEN,
        nullptr, ah, E_DIM, (long)S_LEN * E_DIM, HD_DIM,
        nullptr, nullptr, S_LEN, H_NUM, 1.f, 0);

    // --- O projection + residual x ---
    gemm_fp16<128,128,64,32><<<gp, blk, SM_128>>>(
        ah, E_DIM, 0, 0,  Woh, E_DIM, 0, 0,
        res1, nullptr, E_DIM, 0, 0,
        x, nullptr, E_DIM, 1, 1.f, 0);

    // --- LN1 -> h (fp32 + fp16) ---
    layernorm_rows<<<N_TOK, 256>>>(res1, g1, b1, h, hh);

    // --- FFN1: relu(h @ W1^T + bb1) -> fp16 ---
    dim3 gf1(F_DIM / 128, N_TOK / 128, 1);
    gemm_fp16<128,128,64,32><<<gf1, blk, SM_128>>>(
        hh, E_DIM, 0, 0,  W1h, E_DIM, 0, 0,
        nullptr, fh, F_DIM, 0, 0,
        nullptr, bb1, E_DIM, 1, 1.f, 1);

    // --- FFN2: ffn @ W2^T + bb2 + h ---
    gemm_fp16<128,128,64,32><<<gp, blk, SM_128>>>(
        fh, F_DIM, 0, 0,  W2h, F_DIM, 0, 0,
        res2, nullptr, E_DIM, 0, 0,
        h, bb2, F_DIM, 1, 1.f, 0);

    // --- LN2 -> out ---
    layernorm_rows<<<N_TOK, 256>>>(res2, g2, b2, out, nullptr);
}

// round 11
// speedup vs baseline: 3.3468x; 1.3581x over previous
#include <cuda_runtime.h>
#include <cuda_fp16.h>
#include <math.h>
#include <stdint.h>

typedef __half  f16;
typedef __half2 f162;

// ---------------------------------------------------------------------------
// Problem constants
// ---------------------------------------------------------------------------
#define E_DIM   1024
#define H_NUM   16
#define HD_DIM  64
#define F_DIM   4096
#define B_NUM   4
#define S_LEN   2048
#define N_TOK   (B_NUM * S_LEN)      // 8192
#define BH_NUM  (B_NUM * H_NUM)      // 64
#define LN_EPS  1e-5f

// ---------------------------------------------------------------------------
// Scratch buffers (static device globals) — total ~0.26 GB (P buffer deleted)
// ---------------------------------------------------------------------------
__device__ float g_res1[(size_t)N_TOK * E_DIM];            // 32 MB (also V fp32)
__device__ float g_h   [(size_t)N_TOK * E_DIM];
__device__ float g_res2[(size_t)N_TOK * E_DIM];
__device__ f16 g_xh [(size_t)N_TOK * E_DIM];
__device__ f16 g_Wqh[(size_t)E_DIM * E_DIM];
__device__ f16 g_Wkh[(size_t)E_DIM * E_DIM];
__device__ f16 g_Wvh[(size_t)E_DIM * E_DIM];
__device__ f16 g_Woh[(size_t)E_DIM * E_DIM];
__device__ f16 g_W1h[(size_t)F_DIM * E_DIM];
__device__ f16 g_W2h[(size_t)E_DIM * F_DIM];
__device__ f16 g_Qh [(size_t)N_TOK * E_DIM];
__device__ f16 g_Kh [(size_t)N_TOK * E_DIM];
__device__ f16 g_Vth[(size_t)BH_NUM * HD_DIM * S_LEN];
__device__ f16 g_ah [(size_t)N_TOK * E_DIM];
__device__ f16 g_hh [(size_t)N_TOK * E_DIM];
__device__ f16 g_fh [(size_t)N_TOK * F_DIM];

// ---------------------------------------------------------------------------
// Helpers
// ---------------------------------------------------------------------------
__device__ __forceinline__ uint32_t smem_u32(const void* p) {
    return (uint32_t)__cvta_generic_to_shared(p);
}

__device__ __forceinline__ void ldsm4(uint32_t* r, uint32_t a) {
    asm volatile("ldmatrix.sync.aligned.m8n8.x4.shared.b16 {%0,%1,%2,%3}, [%4];"
        : "=r"(r[0]), "=r"(r[1]), "=r"(r[2]), "=r"(r[3]) : "r"(a));
}

__device__ __forceinline__ void mma16816(float* c, const uint32_t* a, const uint32_t* b) {
    asm volatile(
        "mma.sync.aligned.m16n8k16.row.col.f32.f16.f16.f32 "
        "{%0,%1,%2,%3}, {%4,%5,%6,%7}, {%8,%9}, {%0,%1,%2,%3};"
        : "+f"(c[0]), "+f"(c[1]), "+f"(c[2]), "+f"(c[3])
        : "r"(a[0]), "r"(a[1]), "r"(a[2]), "r"(a[3]), "r"(b[0]), "r"(b[1]));
}

__device__ __forceinline__ void cpasync16(uint32_t dst, const void* src) {
    asm volatile("cp.async.cg.shared.global [%0], [%1], 16;\n" :: "r"(dst), "l"(src));
}
__device__ __forceinline__ void cpasync_commit() {
    asm volatile("cp.async.commit_group;\n");
}
template<int N>
__device__ __forceinline__ void cpasync_wait() {
    asm volatile("cp.async.wait_group %0;\n" :: "n"(N));
}

__device__ __forceinline__ float blockReduceSum256(float v) {
    __shared__ float s[8];
    int lane = threadIdx.x & 31, wid = threadIdx.x >> 5;
    #pragma unroll
    for (int o = 16; o; o >>= 1) v += __shfl_xor_sync(0xffffffffu, v, o);
    __syncthreads();
    if (lane == 0) s[wid] = v;
    __syncthreads();
    float r = s[0];
    #pragma unroll
    for (int i = 1; i < 8; i++) r += s[i];
    return r;
}

__device__ __forceinline__ float blockReduceMax256(float v) {
    __shared__ float s[8];
    int lane = threadIdx.x & 31, wid = threadIdx.x >> 5;
    #pragma unroll
    for (int o = 16; o; o >>= 1) v = fmaxf(v, __shfl_xor_sync(0xffffffffu, v, o));
    __syncthreads();
    if (lane == 0) s[wid] = v;
    __syncthreads();
    float r = s[0];
    #pragma unroll
    for (int i = 1; i < 8; i++) r = fmaxf(r, s[i]);
    return r;
}

// ---------------------------------------------------------------------------
// fp16 tensor-core GEMM with 3-stage cp.async pipeline (unchanged from R10).
// ---------------------------------------------------------------------------
#define GBK    32
#define GLDS   40
#define GSTG   3

template<int BM, int BN, int WM, int WN>
__global__ __launch_bounds__(256, 2) void gemm_fp16(
    const f16* __restrict__ A, int lda, long aOffB, long aOffH,
    const f16* __restrict__ B, int ldb, long bOffB, long bOffH,
    float* Cf32, f16* Ch,
    int ldc, long cOffB, long cOffH,
    const float* __restrict__ residual, const float* __restrict__ bias,
    int K, int nH, float alpha, int relu)
{
    constexpr int WARPS_N = BN / WN;
    constexpr int MF  = WM / 16;
    constexpr int NF  = WN / 8;
    constexpr int NG  = WN / 16;
    constexpr int AIT = (BM * GBK) / (8 * 256);
    constexpr int BIT = (BN * GBK) / (8 * 256);
    constexpr int A_STG = BM * GLDS;
    constexpr int B_STG = BN * GLDS;

    extern __shared__ __align__(16) f16 smemBuf[];
    f16* sA = smemBuf;
    f16* sB = sA + (size_t)GSTG * A_STG;

    const int tid  = threadIdx.x;
    const int warp = tid >> 5, lane = tid & 31;
    const int wr = warp / WARPS_N, wc = warp % WARPS_N;
    const int row0 = blockIdx.y * BM;
    const int col0 = blockIdx.x * BN;

    const int z  = blockIdx.z;
    const int zb = z / nH, zh = z % nH;
    const f16* Az = A + (long)zb * aOffB + (long)zh * aOffH;
    const f16* Bz = B + (long)zb * bOffB + (long)zh * bOffH;
    const long  zC = (long)zb * cOffB + (long)zh * cOffH;

    float acc[MF][NF][4];
    #pragma unroll
    for (int i = 0; i < MF; i++)
        #pragma unroll
        for (int j = 0; j < NF; j++)
            #pragma unroll
            for (int k = 0; k < 4; k++) acc[i][j][k] = 0.f;

    auto issueTile = [&](int kt) {
        const int stage = kt % GSTG;
        const int k0 = kt * GBK;
        #pragma unroll
        for (int i = 0; i < AIT; i++) {
            int idx = tid + i * 256, r = idx >> 2, c = (idx & 3) * 8;
            cpasync16(smem_u32(sA + (uint32_t)((stage * BM + r) * GLDS + c)),
                      Az + (long)(row0 + r) * lda + k0 + c);
        }
        #pragma unroll
        for (int i = 0; i < BIT; i++) {
            int idx = tid + i * 256, r = idx >> 2, c = (idx & 3) * 8;
            cpasync16(smem_u32(sB + (uint32_t)((stage * BN + r) * GLDS + c)),
                      Bz + (long)(col0 + r) * ldb + k0 + c);
        }
    };

    const int KT = K / GBK;

    #pragma unroll
    for (int s = 0; s < GSTG - 1; s++) {
        if (s < KT) issueTile(s);
        cpasync_commit();
    }

    const int aRowL = ((lane >> 3) & 1) * 8 + (lane & 7);
    const int aColL = (lane >> 4) * 8;
    const int bRowL = (lane >> 4) * 8 + (lane & 7);
    const int bColL = ((lane >> 3) & 1) * 8;
    const uint32_t aBase0 = smem_u32(sA) + ((wr * WM + aRowL) * GLDS + aColL) * 2;
    const uint32_t bBase0 = smem_u32(sB) + ((wc * WN + bRowL) * GLDS + bColL) * 2;

    for (int kt = 0; kt < KT; kt++) {
        if (kt == KT - 1) cpasync_wait<0>();
        else              cpasync_wait<GSTG - 2>();
        __syncthreads();

        int nk = kt + GSTG - 1;
        if (nk < KT) issueTile(nk);
        cpasync_commit();

        const int stage = kt % GSTG;
        const uint32_t sOffA = (uint32_t)(stage * A_STG * 2);
        const uint32_t sOffB = (uint32_t)(stage * B_STG * 2);

        #pragma unroll
        for (int kk = 0; kk < 2; kk++) {
            const uint32_t koff = kk * 32;
            uint32_t aR[MF][4];
            #pragma unroll
            for (int mi = 0; mi < MF; mi++)
                ldsm4(aR[mi], aBase0 + sOffA + mi * (16 * GLDS * 2) + koff);
            uint32_t bR[NF][2];
            #pragma unroll
            for (int gi = 0; gi < NG; gi++) {
                uint32_t t4[4];
                ldsm4(t4, bBase0 + sOffB + gi * (16 * GLDS * 2) + koff);
                bR[2 * gi][0] = t4[0]; bR[2 * gi][1] = t4[1];
                bR[2 * gi + 1][0] = t4[2]; bR[2 * gi + 1][1] = t4[3];
            }
            #pragma unroll
            for (int mi = 0; mi < MF; mi++)
                #pragma unroll
                for (int nf = 0; nf < NF; nf++)
                    mma16816(acc[mi][nf], aR[mi], bR[nf]);
        }
    }

    float*       Cz = Cf32 ? Cf32 + zC : nullptr;
    f16*         CH = Ch   ? Ch   + zC : nullptr;
    const float* Rz = residual ? residual + zC : nullptr;

    #pragma unroll
    for (int mi = 0; mi < MF; mi++)
        #pragma unroll
        for (int nf = 0; nf < NF; nf++) {
            int rbase = row0 + wr * WM + mi * 16 + (lane >> 2);
            int c     = col0 + wc * WN + nf * 8 + (lane & 3) * 2;
            #pragma unroll
            for (int half = 0; half < 2; half++) {
                long r = rbase + half * 8;
                float v0 = acc[mi][nf][half * 2 + 0] * alpha;
                float v1 = acc[mi][nf][half * 2 + 1] * alpha;
                if (bias) { v0 += bias[c]; v1 += bias[c + 1]; }
                if (relu) { v0 = fmaxf(v0, 0.f); v1 = fmaxf(v1, 0.f); }
                if (Rz)   { v0 += Rz[r * (long)ldc + c]; v1 += Rz[r * (long)ldc + c + 1]; }
                if (Cz) *(float2*)&Cz[r * (long)ldc + c] = make_float2(v0, v1);
                if (CH) *(f162*)&CH[r * (long)ldc + c] =
                            __floats2half2_rn(v0, v1);
            }
        }
}

// ---------------------------------------------------------------------------
// Flash attention: per (q-tile 128, b*h) CTA. Q resident; loop KV tiles of 64,
// double-buffered cp.async. Online softmax in fp32 regs; P repacked in regs.
// Writes fp16 attn output in [b, s, (h,d)] layout.
// ---------------------------------------------------------------------------
#define FT_QT  128
#define FT_KT  64
#define FLDS   72      // smem row stride (halves) = 64 + 8 pad

__global__ __launch_bounds__(256) void flash_attn(
    const f16* __restrict__ Qg, const f16* __restrict__ Kg,
    const f16* __restrict__ Vtg, f16* __restrict__ Og)
{
    extern __shared__ __align__(16) f16 sm[];
    f16* sQ = sm;                              // [128][72]
    f16* sK = sQ + FT_QT * FLDS;               // [2][64][72]
    f16* sV = sK + 2 * FT_KT * FLDS;           // [2][64][72]

    const int tid = threadIdx.x, warp = tid >> 5, lane = tid & 31;
    const int q0 = blockIdx.x * FT_QT;
    const int bh = blockIdx.y, b = bh >> 4, h = bh & 15;

    const f16* Qz = Qg + ((size_t)b * S_LEN + q0) * E_DIM + h * HD_DIM;
    const f16* Kz = Kg + ((size_t)b * S_LEN) * E_DIM + h * HD_DIM;
    const f16* Vz = Vtg + (size_t)bh * HD_DIM * S_LEN;
    f16* Oz = Og + ((size_t)b * S_LEN + q0) * E_DIM + h * HD_DIM;

    // Q tile: 128 rows x 64 halves = 1024 x 16B
    #pragma unroll
    for (int i = 0; i < 4; i++) {
        int idx = tid + i * 256, r = idx >> 3, g = idx & 7;
        cpasync16(smem_u32(sQ + r * FLDS + g * 8), Qz + (size_t)r * E_DIM + g * 8);
    }
    auto loadKV = [&](int j) {
        const int buf = j & 1;
        const int kv0 = j * FT_KT;
        #pragma unroll
        for (int i = 0; i < 2; i++) {
            int idx = tid + i * 256, r = idx >> 3, g = idx & 7;
            cpasync16(smem_u32(sK + (buf * FT_KT + r) * FLDS + g * 8),
                      Kz + (size_t)(kv0 + r) * E_DIM + g * 8);
            cpasync16(smem_u32(sV + (buf * FT_KT + r) * FLDS + g * 8),
                      Vz + (size_t)r * S_LEN + kv0 + g * 8);
        }
    };
    loadKV(0);
    cpasync_commit();   // group 0 = Q + tile 0

    const int aRowL = ((lane >> 3) & 1) * 8 + (lane & 7);
    const int aColL = (lane >> 4) * 8;
    const int bRowL = (lane >> 4) * 8 + (lane & 7);
    const int bColL = ((lane >> 3) & 1) * 8;
    const uint32_t qBase = smem_u32(sQ) + ((warp * 16 + aRowL) * FLDS + aColL) * 2;
    const uint32_t kBase = smem_u32(sK) + (bRowL * FLDS + bColL) * 2;
    const uint32_t vBase = smem_u32(sV) + (bRowL * FLDS + bColL) * 2;
    const uint32_t bufB = FT_KT * FLDS * 2;    // bytes per buffer

    float o[8][4];
    #pragma unroll
    for (int d = 0; d < 8; d++)
        #pragma unroll
        for (int c = 0; c < 4; c++) o[d][c] = 0.f;
    float mrow[2] = { -1e30f, -1e30f };
    float lrow[2] = { 0.f, 0.f };
    uint32_t aQ[4][4];

    const int NT = S_LEN / FT_KT;   // 32
    for (int j = 0; j < NT; j++) {
        if (j + 1 < NT) { loadKV(j + 1); cpasync_commit(); cpasync_wait<1>(); }
        else            { cpasync_commit(); cpasync_wait<0>(); }
        __syncthreads();

        if (j == 0) {                      // Q fragments: load once
            #pragma unroll
            for (int ks = 0; ks < 4; ks++) ldsm4(aQ[ks], qBase + ks * 32);
        }

        const uint32_t kB = kBase + (uint32_t)(j & 1) * bufB;
        const uint32_t vB = vBase + (uint32_t)(j & 1) * bufB;

        // ---- S = Q K^T ----
        float s[8][4];
        #pragma unroll
        for (int nf = 0; nf < 8; nf++)
            #pragma unroll
            for (int c = 0; c < 4; c++) s[nf][c] = 0.f;
        #pragma unroll
        for (int ks = 0; ks < 4; ks++) {
            #pragma unroll
            for (int gi = 0; gi < 4; gi++) {
                uint32_t t4[4];
                ldsm4(t4, kB + gi * (16 * FLDS * 2) + ks * 32);
                mma16816(s[2 * gi],     aQ[ks], t4);
                mma16816(s[2 * gi + 1], aQ[ks], t4 + 2);
            }
        }
        #pragma unroll
        for (int nf = 0; nf < 8; nf++)
            #pragma unroll
            for (int c = 0; c < 4; c++) s[nf][c] *= 0.125f;

        // ---- online softmax (per row half hf: rows lane>>2 and +8) ----
        #pragma unroll
        for (int hf = 0; hf < 2; hf++) {
            float mx = -1e30f;
            #pragma unroll
            for (int nf = 0; nf < 8; nf++)
                mx = fmaxf(mx, fmaxf(s[nf][2 * hf], s[nf][2 * hf + 1]));
            mx = fmaxf(mx, __shfl_xor_sync(0xffffffffu, mx, 1));
            mx = fmaxf(mx, __shfl_xor_sync(0xffffffffu, mx, 2));
            float mnew = fmaxf(mrow[hf], mx);
            float alpha = __expf(mrow[hf] - mnew);
            mrow[hf] = mnew;
            float rs = 0.f;
            #pragma unroll
            for (int nf = 0; nf < 8; nf++) {
                float p0 = __expf(s[nf][2 * hf]     - mnew);
                float p1 = __expf(s[nf][2 * hf + 1] - mnew);
                s[nf][2 * hf] = p0; s[nf][2 * hf + 1] = p1;
                rs += p0 + p1;
            }
            rs += __shfl_xor_sync(0xffffffffu, rs, 1);
            rs += __shfl_xor_sync(0xffffffffu, rs, 2);
            lrow[hf] = lrow[hf] * alpha + rs;
            #pragma unroll
            for (int df = 0; df < 8; df++) {
                o[df][2 * hf]     *= alpha;
                o[df][2 * hf + 1] *= alpha;
            }
        }

        // ---- repack P (fp32 C-frags) -> fp16 A-frags in registers ----
        uint32_t aP[4][4];
        #pragma unroll
        for (int ks = 0; ks < 4; ks++) {
            f162 h0 = __floats2half2_rn(s[2 * ks][0],     s[2 * ks][1]);
            f162 h1 = __floats2half2_rn(s[2 * ks][2],     s[2 * ks][3]);
            f162 h2 = __floats2half2_rn(s[2 * ks + 1][0], s[2 * ks + 1][1]);
            f162 h3 = __floats2half2_rn(s[2 * ks + 1][2], s[2 * ks + 1][3]);
            aP[ks][0] = *(uint32_t*)&h0; aP[ks][1] = *(uint32_t*)&h1;
            aP[ks][2] = *(uint32_t*)&h2; aP[ks][3] = *(uint32_t*)&h3;
        }

        // ---- O += P V  (B from Vt tile [d][kv]) ----
        #pragma unroll
        for (int ks = 0; ks < 4; ks++) {
            #pragma unroll
            for (int gi = 0; gi < 4; gi++) {
                uint32_t t4[4];
                ldsm4(t4, vB + gi * (16 * FLDS * 2) + ks * 32);
                mma16816(o[2 * gi],     aP[ks], t4);
                mma16816(o[2 * gi + 1], aP[ks], t4 + 2);
            }
        }
        __syncthreads();   // done reading buffers before next-iter issue
    }

    // ---- epilogue: O / l -> fp16 ----
    #pragma unroll
    for (int hf = 0; hf < 2; hf++) {
        float inv = 1.f / lrow[hf];
        size_t r = (size_t)(warp * 16 + (lane >> 2) + hf * 8);
        #pragma unroll
        for (int df = 0; df < 8; df++) {
            int c = df * 8 + (lane & 3) * 2;
            *(f162*)&Oz[r * E_DIM + c] =
                __floats2half2_rn(o[df][2 * hf] * inv, o[df][2 * hf + 1] * inv);
        }
    }
}

// ---------------------------------------------------------------------------
// fp32 -> fp16 conversion (4 elems/thread)
// ---------------------------------------------------------------------------
__global__ void cvt4(const float* __restrict__ in, f16* __restrict__ out, size_t n4)
{
    size_t i = (size_t)blockIdx.x * blockDim.x + threadIdx.x;
    if (i >= n4) return;
    float4 v = ((const float4*)in)[i];
    ((f162*)out)[2 * i + 0] = __floats2half2_rn(v.x, v.y);
    ((f162*)out)[2 * i + 1] = __floats2half2_rn(v.z, v.w);
}

// ---------------------------------------------------------------------------
// V [b,s,(h,d)] fp32 -> Vt [(b,h), d, s] fp16
// ---------------------------------------------------------------------------
__global__ void transpose_cvt_v(const float* __restrict__ V, f16* __restrict__ Vt)
{
    __shared__ float t[32][33];
    int z = blockIdx.z, b = z >> 4, h = z & 15;
    int s0 = blockIdx.x * 32, d0 = blockIdx.y * 32;
    #pragma unroll
    for (int j = 0; j < 4; j++) {
        int s = s0 + threadIdx.y + j * 8;
        t[threadIdx.y + j * 8][threadIdx.x] =
            V[(size_t)(b * S_LEN + s) * E_DIM + h * HD_DIM + d0 + threadIdx.x];
    }
    __syncthreads();
    #pragma unroll
    for (int j = 0; j < 4; j++) {
        int d = d0 + threadIdx.y + j * 8;
        Vt[((size_t)z * HD_DIM + d) * S_LEN + s0 + threadIdx.x] =
            __float2half_rn(t[threadIdx.x][threadIdx.y + j * 8]);
    }
}

// ---------------------------------------------------------------------------
// LayerNorm (E=1024), fp32 out + optional fp16 out
// ---------------------------------------------------------------------------
__global__ __launch_bounds__(256) void layernorm_rows(
    const float* __restrict__ in,
    const float* __restrict__ g, const float* __restrict__ b,
    float* __restrict__ out, f16* __restrict__ oh)
{
    size_t row = blockIdx.x;
    const float4* x4 = (const float4*)(in + row * E_DIM);
    float4 v = x4[threadIdx.x];

    float s  = v.x + v.y + v.z + v.w;
    float ss = v.x * v.x + v.y * v.y + v.z * v.z + v.w * v.w;
    s  = blockReduceSum256(s);
    ss = blockReduceSum256(ss);

    const float invE = 1.f / (float)E_DIM;
    float mu   = s * invE;
    float var  = ss * invE - mu * mu;
    float rstd = rsqrtf(var + LN_EPS);

    float4 gv = ((const float4*)g)[threadIdx.x];
    float4 bv = ((const float4*)b)[threadIdx.x];
    float4 o;
    o.x = (v.x - mu) * rstd * gv.x + bv.x;
    o.y = (v.y - mu) * rstd * gv.y + bv.y;
    o.z = (v.z - mu) * rstd * gv.z + bv.z;
    o.w = (v.w - mu) * rstd * gv.w + bv.w;
    ((float4*)(out + row * E_DIM))[threadIdx.x] = o;

    if (oh) {
        f162* ph = (f162*)(oh + row * E_DIM);
        ph[2 * threadIdx.x + 0] = __floats2half2_rn(o.x, o.y);
        ph[2 * threadIdx.x + 1] = __floats2half2_rn(o.z, o.w);
    }
}

// ---------------------------------------------------------------------------
// Launch
// Inputs: 0:x 1:Wq 2:Wk 3:Wv 4:Wo 5:g1 6:b1 7:g2 8:b2 9:W1 10:bb1 11:W2 12:bb2
// ---------------------------------------------------------------------------
#define SYMADDR(v, s) cudaGetSymbolAddress((void**)&v, s)
#define GEMM_SMEM(BM, BN) (GSTG * ((BM) + (BN)) * GLDS * 2)
#define FLASH_SMEM ((FT_QT + 4 * FT_KT) * FLDS * 2)   // 55296 B

extern "C" void kernel_launch(void* const* d_in, const int* in_sizes, int n_in,
                              void* d_out, int out_size)
{
    const float* x   = (const float*)d_in[0];
    const float* Wq  = (const float*)d_in[1];
    const float* Wk  = (const float*)d_in[2];
    const float* Wv  = (const float*)d_in[3];
    const float* Wo  = (const float*)d_in[4];
    const float* g1  = (const float*)d_in[5];
    const float* b1  = (const float*)d_in[6];
    const float* g2  = (const float*)d_in[7];
    const float* b2  = (const float*)d_in[8];
    const float* W1  = (const float*)d_in[9];
    const float* bb1 = (const float*)d_in[10];
    const float* W2  = (const float*)d_in[11];
    const float* bb2 = (const float*)d_in[12];
    float* out = (float*)d_out;

    float *res1, *h, *res2;
    f16 *xh, *Wqh, *Wkh, *Wvh, *Woh, *W1h, *W2h;
    f16 *Qh, *Kh, *Vth, *ah, *hh, *fh;
    SYMADDR(res1, g_res1);
    SYMADDR(h, g_h); SYMADDR(res2, g_res2);
    SYMADDR(xh, g_xh);
    SYMADDR(Wqh, g_Wqh); SYMADDR(Wkh, g_Wkh);
    SYMADDR(Wvh, g_Wvh); SYMADDR(Woh, g_Woh);
    SYMADDR(W1h, g_W1h); SYMADDR(W2h, g_W2h);
    SYMADDR(Qh, g_Qh); SYMADDR(Kh, g_Kh);
    SYMADDR(Vth, g_Vth);
    SYMADDR(ah, g_ah); SYMADDR(hh, g_hh); SYMADDR(fh, g_fh);

    float* Vf32 = res1;                 // V projection parks in res1 (free here)

    const int SM_128 = GEMM_SMEM(128, 128);   // 61440
    cudaFuncSetAttribute(gemm_fp16<128,128,64,32>,
                         cudaFuncAttributeMaxDynamicSharedMemorySize, SM_128);
    cudaFuncSetAttribute(flash_attn,
                         cudaFuncAttributeMaxDynamicSharedMemorySize, FLASH_SMEM);

    dim3 blk(256);

    // --- convert inputs/weights to fp16 ---
    auto cvtLaunch = [&](const float* src, f16* dst, size_t n) {
        size_t n4 = n / 4;
        cvt4<<<(unsigned)((n4 + 255) / 256), 256>>>(src, dst, n4);
    };
    cvtLaunch(x,  xh,  (size_t)N_TOK * E_DIM);
    cvtLaunch(Wq, Wqh, (size_t)E_DIM * E_DIM);
    cvtLaunch(Wk, Wkh, (size_t)E_DIM * E_DIM);
    cvtLaunch(Wv, Wvh, (size_t)E_DIM * E_DIM);
    cvtLaunch(Wo, Woh, (size_t)E_DIM * E_DIM);
    cvtLaunch(W1, W1h, (size_t)F_DIM * E_DIM);
    cvtLaunch(W2, W2h, (size_t)E_DIM * F_DIM);

    // --- QKV projections ---
    dim3 gp(E_DIM / 128, N_TOK / 128, 1);
    gemm_fp16<128,128,64,32><<<gp, blk, SM_128>>>(
        xh, E_DIM, 0, 0,  Wqh, E_DIM, 0, 0,
        nullptr, Qh, E_DIM, 0, 0,
        nullptr, nullptr, E_DIM, 1, 1.f, 0);
    gemm_fp16<128,128,64,32><<<gp, blk, SM_128>>>(
        xh, E_DIM, 0, 0,  Wkh, E_DIM, 0, 0,
        nullptr, Kh, E_DIM, 0, 0,
        nullptr, nullptr, E_DIM, 1, 1.f, 0);
    gemm_fp16<128,128,64,32><<<gp, blk, SM_128>>>(
        xh, E_DIM, 0, 0,  Wvh, E_DIM, 0, 0,
        Vf32, nullptr, E_DIM, 0, 0,
        nullptr, nullptr, E_DIM, 1, 1.f, 0);

    // --- V transpose + convert ---
    transpose_cvt_v<<<dim3(S_LEN / 32, HD_DIM / 32, BH_NUM), dim3(32, 8)>>>(Vf32, Vth);

    // --- fused flash attention -> ah fp16 [b,s,(h,d)] ---
    flash_attn<<<dim3(S_LEN / FT_QT, BH_NUM), blk, FLASH_SMEM>>>(Qh, Kh, Vth, ah);

    // --- O projection + residual x ---
    gemm_fp16<128,128,64,32><<<gp, blk, SM_128>>>(
        ah, E_DIM, 0, 0,  Woh, E_DIM, 0, 0,
        res1, nullptr, E_DIM, 0, 0,
        x, nullptr, E_DIM, 1, 1.f, 0);

    // --- LN1 -> h (fp32 + fp16) ---
    layernorm_rows<<<N_TOK, 256>>>(res1, g1, b1, h, hh);

    // --- FFN1: relu(h @ W1^T + bb1) -> fp16 ---
    dim3 gf1(F_DIM / 128, N_TOK / 128, 1);
    gemm_fp16<128,128,64,32><<<gf1, blk, SM_128>>>(
        hh, E_DIM, 0, 0,  W1h, E_DIM, 0, 0,
        nullptr, fh, F_DIM, 0, 0,
        nullptr, bb1, E_DIM, 1, 1.f, 1);

    // --- FFN2: ffn @ W2^T + bb2 + h ---
    gemm_fp16<128,128,64,32><<<gp, blk, SM_128>>>(
        fh, F_DIM, 0, 0,  W2h, F_DIM, 0, 0,
        res2, nullptr, E_DIM, 0, 0,
        h, bb2, F_DIM, 1, 1.f, 0);

    // --- LN2 -> out ---
    layernorm_rows<<<N_TOK, 256>>>(res2, g2, b2, out, nullptr);
}

// round 12
// speedup vs baseline: 3.4955x; 1.0444x over previous
#include <cuda_runtime.h>
#include <cuda_fp16.h>
#include <math.h>
#include <stdint.h>

typedef __half  f16;
typedef __half2 f162;

// ---------------------------------------------------------------------------
// Problem constants
// ---------------------------------------------------------------------------
#define E_DIM   1024
#define H_NUM   16
#define HD_DIM  64
#define F_DIM   4096
#define B_NUM   4
#define S_LEN   2048
#define N_TOK   (B_NUM * S_LEN)      // 8192
#define BH_NUM  (B_NUM * H_NUM)      // 64
#define LN_EPS  1e-5f
#define QKV_LD  (3 * E_DIM)          // 3072

// ---------------------------------------------------------------------------
// Scratch buffers (static device globals)
// ---------------------------------------------------------------------------
__device__ float g_res1[(size_t)N_TOK * E_DIM];            // 32 MB
__device__ float g_h   [(size_t)N_TOK * E_DIM];
__device__ float g_res2[(size_t)N_TOK * E_DIM];
__device__ f16 g_xh   [(size_t)N_TOK * E_DIM];
__device__ f16 g_Wqkvh[(size_t)3 * E_DIM * E_DIM];         // concat [3072,1024]
__device__ f16 g_Woh  [(size_t)E_DIM * E_DIM];
__device__ f16 g_W1h  [(size_t)F_DIM * E_DIM];
__device__ f16 g_W2h  [(size_t)E_DIM * F_DIM];
__device__ f16 g_qkv  [(size_t)N_TOK * 3 * E_DIM];         // 48 MB [tok, 3072]
__device__ f16 g_Vth  [(size_t)BH_NUM * HD_DIM * S_LEN];
__device__ f16 g_ah   [(size_t)N_TOK * E_DIM];
__device__ f16 g_hh   [(size_t)N_TOK * E_DIM];
__device__ f16 g_fh   [(size_t)N_TOK * F_DIM];

// ---------------------------------------------------------------------------
// Helpers
// ---------------------------------------------------------------------------
__device__ __forceinline__ uint32_t smem_u32(const void* p) {
    return (uint32_t)__cvta_generic_to_shared(p);
}

__device__ __forceinline__ void ldsm4(uint32_t* r, uint32_t a) {
    asm volatile("ldmatrix.sync.aligned.m8n8.x4.shared.b16 {%0,%1,%2,%3}, [%4];"
        : "=r"(r[0]), "=r"(r[1]), "=r"(r[2]), "=r"(r[3]) : "r"(a));
}

__device__ __forceinline__ void mma16816(float* c, const uint32_t* a, const uint32_t* b) {
    asm volatile(
        "mma.sync.aligned.m16n8k16.row.col.f32.f16.f16.f32 "
        "{%0,%1,%2,%3}, {%4,%5,%6,%7}, {%8,%9}, {%0,%1,%2,%3};"
        : "+f"(c[0]), "+f"(c[1]), "+f"(c[2]), "+f"(c[3])
        : "r"(a[0]), "r"(a[1]), "r"(a[2]), "r"(a[3]), "r"(b[0]), "r"(b[1]));
}

__device__ __forceinline__ void cpasync16(uint32_t dst, const void* src) {
    asm volatile("cp.async.cg.shared.global [%0], [%1], 16;\n" :: "r"(dst), "l"(src));
}
__device__ __forceinline__ void cpasync_commit() {
    asm volatile("cp.async.commit_group;\n");
}
template<int N>
__device__ __forceinline__ void cpasync_wait() {
    asm volatile("cp.async.wait_group %0;\n" :: "n"(N));
}

__device__ __forceinline__ float blockReduceSum256(float v) {
    __shared__ float s[8];
    int lane = threadIdx.x & 31, wid = threadIdx.x >> 5;
    #pragma unroll
    for (int o = 16; o; o >>= 1) v += __shfl_xor_sync(0xffffffffu, v, o);
    __syncthreads();
    if (lane == 0) s[wid] = v;
    __syncthreads();
    float r = s[0];
    #pragma unroll
    for (int i = 1; i < 8; i++) r += s[i];
    return r;
}

// ---------------------------------------------------------------------------
// fp16 tensor-core GEMM with 3-stage cp.async pipeline (proven in R10/R11).
// ---------------------------------------------------------------------------
#define GBK    32
#define GLDS   40
#define GSTG   3

template<int BM, int BN, int WM, int WN>
__global__ __launch_bounds__(256, 2) void gemm_fp16(
    const f16* __restrict__ A, int lda, long aOffB, long aOffH,
    const f16* __restrict__ B, int ldb, long bOffB, long bOffH,
    float* Cf32, f16* Ch,
    int ldc, long cOffB, long cOffH,
    const float* __restrict__ residual, const float* __restrict__ bias,
    int K, int nH, float alpha, int relu)
{
    constexpr int WARPS_N = BN / WN;
    constexpr int MF  = WM / 16;
    constexpr int NF  = WN / 8;
    constexpr int NG  = WN / 16;
    constexpr int AIT = (BM * GBK) / (8 * 256);
    constexpr int BIT = (BN * GBK) / (8 * 256);
    constexpr int A_STG = BM * GLDS;
    constexpr int B_STG = BN * GLDS;

    extern __shared__ __align__(16) f16 smemBuf[];
    f16* sA = smemBuf;
    f16* sB = sA + (size_t)GSTG * A_STG;

    const int tid  = threadIdx.x;
    const int warp = tid >> 5, lane = tid & 31;
    const int wr = warp / WARPS_N, wc = warp % WARPS_N;
    const int row0 = blockIdx.y * BM;
    const int col0 = blockIdx.x * BN;

    const int z  = blockIdx.z;
    const int zb = z / nH, zh = z % nH;
    const f16* Az = A + (long)zb * aOffB + (long)zh * aOffH;
    const f16* Bz = B + (long)zb * bOffB + (long)zh * bOffH;
    const long  zC = (long)zb * cOffB + (long)zh * cOffH;

    float acc[MF][NF][4];
    #pragma unroll
    for (int i = 0; i < MF; i++)
        #pragma unroll
        for (int j = 0; j < NF; j++)
            #pragma unroll
            for (int k = 0; k < 4; k++) acc[i][j][k] = 0.f;

    auto issueTile = [&](int kt) {
        const int stage = kt % GSTG;
        const int k0 = kt * GBK;
        #pragma unroll
        for (int i = 0; i < AIT; i++) {
            int idx = tid + i * 256, r = idx >> 2, c = (idx & 3) * 8;
            cpasync16(smem_u32(sA + (uint32_t)((stage * BM + r) * GLDS + c)),
                      Az + (long)(row0 + r) * lda + k0 + c);
        }
        #pragma unroll
        for (int i = 0; i < BIT; i++) {
            int idx = tid + i * 256, r = idx >> 2, c = (idx & 3) * 8;
            cpasync16(smem_u32(sB + (uint32_t)((stage * BN + r) * GLDS + c)),
                      Bz + (long)(col0 + r) * ldb + k0 + c);
        }
    };

    const int KT = K / GBK;

    #pragma unroll
    for (int s = 0; s < GSTG - 1; s++) {
        if (s < KT) issueTile(s);
        cpasync_commit();
    }

    const int aRowL = ((lane >> 3) & 1) * 8 + (lane & 7);
    const int aColL = (lane >> 4) * 8;
    const int bRowL = (lane >> 4) * 8 + (lane & 7);
    const int bColL = ((lane >> 3) & 1) * 8;
    const uint32_t aBase0 = smem_u32(sA) + ((wr * WM + aRowL) * GLDS + aColL) * 2;
    const uint32_t bBase0 = smem_u32(sB) + ((wc * WN + bRowL) * GLDS + bColL) * 2;

    for (int kt = 0; kt < KT; kt++) {
        if (kt == KT - 1) cpasync_wait<0>();
        else              cpasync_wait<GSTG - 2>();
        __syncthreads();

        int nk = kt + GSTG - 1;
        if (nk < KT) issueTile(nk);
        cpasync_commit();

        const int stage = kt % GSTG;
        const uint32_t sOffA = (uint32_t)(stage * A_STG * 2);
        const uint32_t sOffB = (uint32_t)(stage * B_STG * 2);

        #pragma unroll
        for (int kk = 0; kk < 2; kk++) {
            const uint32_t koff = kk * 32;
            uint32_t aR[MF][4];
            #pragma unroll
            for (int mi = 0; mi < MF; mi++)
                ldsm4(aR[mi], aBase0 + sOffA + mi * (16 * GLDS * 2) + koff);
            uint32_t bR[NF][2];
            #pragma unroll
            for (int gi = 0; gi < NG; gi++) {
                uint32_t t4[4];
                ldsm4(t4, bBase0 + sOffB + gi * (16 * GLDS * 2) + koff);
                bR[2 * gi][0] = t4[0]; bR[2 * gi][1] = t4[1];
                bR[2 * gi + 1][0] = t4[2]; bR[2 * gi + 1][1] = t4[3];
            }
            #pragma unroll
            for (int mi = 0; mi < MF; mi++)
                #pragma unroll
                for (int nf = 0; nf < NF; nf++)
                    mma16816(acc[mi][nf], aR[mi], bR[nf]);
        }
    }

    float*       Cz = Cf32 ? Cf32 + zC : nullptr;
    f16*         CH = Ch   ? Ch   + zC : nullptr;
    const float* Rz = residual ? residual + zC : nullptr;

    #pragma unroll
    for (int mi = 0; mi < MF; mi++)
        #pragma unroll
        for (int nf = 0; nf < NF; nf++) {
            int rbase = row0 + wr * WM + mi * 16 + (lane >> 2);
            int c     = col0 + wc * WN + nf * 8 + (lane & 3) * 2;
            #pragma unroll
            for (int half = 0; half < 2; half++) {
                long r = rbase + half * 8;
                float v0 = acc[mi][nf][half * 2 + 0] * alpha;
                float v1 = acc[mi][nf][half * 2 + 1] * alpha;
                if (bias) { v0 += bias[c]; v1 += bias[c + 1]; }
                if (relu) { v0 = fmaxf(v0, 0.f); v1 = fmaxf(v1, 0.f); }
                if (Rz)   { v0 += Rz[r * (long)ldc + c]; v1 += Rz[r * (long)ldc + c + 1]; }
                if (Cz) *(float2*)&Cz[r * (long)ldc + c] = make_float2(v0, v1);
                if (CH) *(f162*)&CH[r * (long)ldc + c] =
                            __floats2half2_rn(v0, v1);
            }
        }
}

// ---------------------------------------------------------------------------
// Flash attention (proven in R11), Q/K sourced from fused qkv buffer
// (row stride QKV_LD). Writes fp16 attn output in [b, s, (h,d)] layout.
// ---------------------------------------------------------------------------
#define FT_QT  128
#define FT_KT  64
#define FLDS   72

__global__ __launch_bounds__(256) void flash_attn(
    const f16* __restrict__ QKVg, const f16* __restrict__ Vtg,
    f16* __restrict__ Og)
{
    extern __shared__ __align__(16) f16 sm[];
    f16* sQ = sm;                              // [128][72]
    f16* sK = sQ + FT_QT * FLDS;               // [2][64][72]
    f16* sV = sK + 2 * FT_KT * FLDS;           // [2][64][72]

    const int tid = threadIdx.x, warp = tid >> 5, lane = tid & 31;
    const int q0 = blockIdx.x * FT_QT;
    const int bh = blockIdx.y, b = bh >> 4, h = bh & 15;

    const f16* Qz = QKVg + ((size_t)b * S_LEN + q0) * QKV_LD + h * HD_DIM;
    const f16* Kz = QKVg + ((size_t)b * S_LEN) * QKV_LD + E_DIM + h * HD_DIM;
    const f16* Vz = Vtg + (size_t)bh * HD_DIM * S_LEN;
    f16* Oz = Og + ((size_t)b * S_LEN + q0) * E_DIM + h * HD_DIM;

    #pragma unroll
    for (int i = 0; i < 4; i++) {
        int idx = tid + i * 256, r = idx >> 3, g = idx & 7;
        cpasync16(smem_u32(sQ + r * FLDS + g * 8), Qz + (size_t)r * QKV_LD + g * 8);
    }
    auto loadKV = [&](int j) {
        const int buf = j & 1;
        const int kv0 = j * FT_KT;
        #pragma unroll
        for (int i = 0; i < 2; i++) {
            int idx = tid + i * 256, r = idx >> 3, g = idx & 7;
            cpasync16(smem_u32(sK + (buf * FT_KT + r) * FLDS + g * 8),
                      Kz + (size_t)(kv0 + r) * QKV_LD + g * 8);
            cpasync16(smem_u32(sV + (buf * FT_KT + r) * FLDS + g * 8),
                      Vz + (size_t)r * S_LEN + kv0 + g * 8);
        }
    };
    loadKV(0);
    cpasync_commit();

    const int aRowL = ((lane >> 3) & 1) * 8 + (lane & 7);
    const int aColL = (lane >> 4) * 8;
    const int bRowL = (lane >> 4) * 8 + (lane & 7);
    const int bColL = ((lane >> 3) & 1) * 8;
    const uint32_t qBase = smem_u32(sQ) + ((warp * 16 + aRowL) * FLDS + aColL) * 2;
    const uint32_t kBase = smem_u32(sK) + (bRowL * FLDS + bColL) * 2;
    const uint32_t vBase = smem_u32(sV) + (bRowL * FLDS + bColL) * 2;
    const uint32_t bufB = FT_KT * FLDS * 2;

    float o[8][4];
    #pragma unroll
    for (int d = 0; d < 8; d++)
        #pragma unroll
        for (int c = 0; c < 4; c++) o[d][c] = 0.f;
    float mrow[2] = { -1e30f, -1e30f };
    float lrow[2] = { 0.f, 0.f };
    uint32_t aQ[4][4];

    const int NT = S_LEN / FT_KT;   // 32
    for (int j = 0; j < NT; j++) {
        if (j + 1 < NT) { loadKV(j + 1); cpasync_commit(); cpasync_wait<1>(); }
        else            { cpasync_commit(); cpasync_wait<0>(); }
        __syncthreads();

        if (j == 0) {
            #pragma unroll
            for (int ks = 0; ks < 4; ks++) ldsm4(aQ[ks], qBase + ks * 32);
        }

        const uint32_t kB = kBase + (uint32_t)(j & 1) * bufB;
        const uint32_t vB = vBase + (uint32_t)(j & 1) * bufB;

        float s[8][4];
        #pragma unroll
        for (int nf = 0; nf < 8; nf++)
            #pragma unroll
            for (int c = 0; c < 4; c++) s[nf][c] = 0.f;
        #pragma unroll
        for (int ks = 0; ks < 4; ks++) {
            #pragma unroll
            for (int gi = 0; gi < 4; gi++) {
                uint32_t t4[4];
                ldsm4(t4, kB + gi * (16 * FLDS * 2) + ks * 32);
                mma16816(s[2 * gi],     aQ[ks], t4);
                mma16816(s[2 * gi + 1], aQ[ks], t4 + 2);
            }
        }
        #pragma unroll
        for (int nf = 0; nf < 8; nf++)
            #pragma unroll
            for (int c = 0; c < 4; c++) s[nf][c] *= 0.125f;

        #pragma unroll
        for (int hf = 0; hf < 2; hf++) {
            float mx = -1e30f;
            #pragma unroll
            for (int nf = 0; nf < 8; nf++)
                mx = fmaxf(mx, fmaxf(s[nf][2 * hf], s[nf][2 * hf + 1]));
            mx = fmaxf(mx, __shfl_xor_sync(0xffffffffu, mx, 1));
            mx = fmaxf(mx, __shfl_xor_sync(0xffffffffu, mx, 2));
            float mnew = fmaxf(mrow[hf], mx);
            float alpha = __expf(mrow[hf] - mnew);
            mrow[hf] = mnew;
            float rs = 0.f;
            #pragma unroll
            for (int nf = 0; nf < 8; nf++) {
                float p0 = __expf(s[nf][2 * hf]     - mnew);
                float p1 = __expf(s[nf][2 * hf + 1] - mnew);
                s[nf][2 * hf] = p0; s[nf][2 * hf + 1] = p1;
                rs += p0 + p1;
            }
            rs += __shfl_xor_sync(0xffffffffu, rs, 1);
            rs += __shfl_xor_sync(0xffffffffu, rs, 2);
            lrow[hf] = lrow[hf] * alpha + rs;
            #pragma unroll
            for (int df = 0; df < 8; df++) {
                o[df][2 * hf]     *= alpha;
                o[df][2 * hf + 1] *= alpha;
            }
        }

        uint32_t aP[4][4];
        #pragma unroll
        for (int ks = 0; ks < 4; ks++) {
            f162 h0 = __floats2half2_rn(s[2 * ks][0],     s[2 * ks][1]);
            f162 h1 = __floats2half2_rn(s[2 * ks][2],     s[2 * ks][3]);
            f162 h2 = __floats2half2_rn(s[2 * ks + 1][0], s[2 * ks + 1][1]);
            f162 h3 = __floats2half2_rn(s[2 * ks + 1][2], s[2 * ks + 1][3]);
            aP[ks][0] = *(uint32_t*)&h0; aP[ks][1] = *(uint32_t*)&h1;
            aP[ks][2] = *(uint32_t*)&h2; aP[ks][3] = *(uint32_t*)&h3;
        }

        #pragma unroll
        for (int ks = 0; ks < 4; ks++) {
            #pragma unroll
            for (int gi = 0; gi < 4; gi++) {
                uint32_t t4[4];
                ldsm4(t4, vB + gi * (16 * FLDS * 2) + ks * 32);
                mma16816(o[2 * gi],     aP[ks], t4);
                mma16816(o[2 * gi + 1], aP[ks], t4 + 2);
            }
        }
        __syncthreads();
    }

    #pragma unroll
    for (int hf = 0; hf < 2; hf++) {
        float inv = 1.f / lrow[hf];
        size_t r = (size_t)(warp * 16 + (lane >> 2) + hf * 8);
        #pragma unroll
        for (int df = 0; df < 8; df++) {
            int c = df * 8 + (lane & 3) * 2;
            *(f162*)&Oz[r * E_DIM + c] =
                __floats2half2_rn(o[df][2 * hf] * inv, o[df][2 * hf + 1] * inv);
        }
    }
}

// ---------------------------------------------------------------------------
// fp32 -> fp16 conversion (4 elems/thread)
// ---------------------------------------------------------------------------
__global__ void cvt4(const float* __restrict__ in, f16* __restrict__ out, size_t n4)
{
    size_t i = (size_t)blockIdx.x * blockDim.x + threadIdx.x;
    if (i >= n4) return;
    float4 v = ((const float4*)in)[i];
    ((f162*)out)[2 * i + 0] = __floats2half2_rn(v.x, v.y);
    ((f162*)out)[2 * i + 1] = __floats2half2_rn(v.z, v.w);
}

// ---------------------------------------------------------------------------
// V slice of fused qkv [tok, 3072] f16 -> Vt [(b,h), d, s] f16
// ---------------------------------------------------------------------------
__global__ void transpose_v16(const f16* __restrict__ QKV, f16* __restrict__ Vt)
{
    __shared__ f16 t[32][40];
    int z = blockIdx.z, b = z >> 4, h = z & 15;
    int s0 = blockIdx.x * 32, d0 = blockIdx.y * 32;
    #pragma unroll
    for (int j = 0; j < 4; j++) {
        int s = s0 + threadIdx.y + j * 8;
        t[threadIdx.y + j * 8][threadIdx.x] =
            QKV[((size_t)b * S_LEN + s) * QKV_LD + 2 * E_DIM + h * HD_DIM + d0 + threadIdx.x];
    }
    __syncthreads();
    #pragma unroll
    for (int j = 0; j < 4; j++) {
        int d = d0 + threadIdx.y + j * 8;
        Vt[((size_t)z * HD_DIM + d) * S_LEN + s0 + threadIdx.x] =
            t[threadIdx.x][threadIdx.y + j * 8];
    }
}

// ---------------------------------------------------------------------------
// LayerNorm (E=1024), fp32 out + optional fp16 out
// ---------------------------------------------------------------------------
__global__ __launch_bounds__(256) void layernorm_rows(
    const float* __restrict__ in,
    const float* __restrict__ g, const float* __restrict__ b,
    float* __restrict__ out, f16* __restrict__ oh)
{
    size_t row = blockIdx.x;
    const float4* x4 = (const float4*)(in + row * E_DIM);
    float4 v = x4[threadIdx.x];

    float s  = v.x + v.y + v.z + v.w;
    float ss = v.x * v.x + v.y * v.y + v.z * v.z + v.w * v.w;
    s  = blockReduceSum256(s);
    ss = blockReduceSum256(ss);

    const float invE = 1.f / (float)E_DIM;
    float mu   = s * invE;
    float var  = ss * invE - mu * mu;
    float rstd = rsqrtf(var + LN_EPS);

    float4 gv = ((const float4*)g)[threadIdx.x];
    float4 bv = ((const float4*)b)[threadIdx.x];
    float4 o;
    o.x = (v.x - mu) * rstd * gv.x + bv.x;
    o.y = (v.y - mu) * rstd * gv.y + bv.y;
    o.z = (v.z - mu) * rstd * gv.z + bv.z;
    o.w = (v.w - mu) * rstd * gv.w + bv.w;
    ((float4*)(out + row * E_DIM))[threadIdx.x] = o;

    if (oh) {
        f162* ph = (f162*)(oh + row * E_DIM);
        ph[2 * threadIdx.x + 0] = __floats2half2_rn(o.x, o.y);
        ph[2 * threadIdx.x + 1] = __floats2half2_rn(o.z, o.w);
    }
}

// ---------------------------------------------------------------------------
// Launch
// Inputs: 0:x 1:Wq 2:Wk 3:Wv 4:Wo 5:g1 6:b1 7:g2 8:b2 9:W1 10:bb1 11:W2 12:bb2
// ---------------------------------------------------------------------------
#define SYMADDR(v, s) cudaGetSymbolAddress((void**)&v, s)
#define GEMM_SMEM(BM, BN) (GSTG * ((BM) + (BN)) * GLDS * 2)
#define FLASH_SMEM ((FT_QT + 4 * FT_KT) * FLDS * 2)   // 55296 B

extern "C" void kernel_launch(void* const* d_in, const int* in_sizes, int n_in,
                              void* d_out, int out_size)
{
    const float* x   = (const float*)d_in[0];
    const float* Wq  = (const float*)d_in[1];
    const float* Wk  = (const float*)d_in[2];
    const float* Wv  = (const float*)d_in[3];
    const float* Wo  = (const float*)d_in[4];
    const float* g1  = (const float*)d_in[5];
    const float* b1  = (const float*)d_in[6];
    const float* g2  = (const float*)d_in[7];
    const float* b2  = (const float*)d_in[8];
    const float* W1  = (const float*)d_in[9];
    const float* bb1 = (const float*)d_in[10];
    const float* W2  = (const float*)d_in[11];
    const float* bb2 = (const float*)d_in[12];
    float* out = (float*)d_out;

    float *res1, *h, *res2;
    f16 *xh, *Wqkvh, *Woh, *W1h, *W2h;
    f16 *qkv, *Vth, *ah, *hh, *fh;
    SYMADDR(res1, g_res1);
    SYMADDR(h, g_h); SYMADDR(res2, g_res2);
    SYMADDR(xh, g_xh);
    SYMADDR(Wqkvh, g_Wqkvh); SYMADDR(Woh, g_Woh);
    SYMADDR(W1h, g_W1h); SYMADDR(W2h, g_W2h);
    SYMADDR(qkv, g_qkv); SYMADDR(Vth, g_Vth);
    SYMADDR(ah, g_ah); SYMADDR(hh, g_hh); SYMADDR(fh, g_fh);

    const int SM_128 = GEMM_SMEM(128, 128);   // 61440
    cudaFuncSetAttribute(gemm_fp16<128,128,64,32>,
                         cudaFuncAttributeMaxDynamicSharedMemorySize, SM_128);
    cudaFuncSetAttribute(flash_attn,
                         cudaFuncAttributeMaxDynamicSharedMemorySize, FLASH_SMEM);

    dim3 blk(256);

    // --- convert inputs/weights to fp16 (Wq/Wk/Wv concat into Wqkvh) ---
    auto cvtLaunch = [&](const float* src, f16* dst, size_t n) {
        size_t n4 = n / 4;
        cvt4<<<(unsigned)((n4 + 255) / 256), 256>>>(src, dst, n4);
    };
    cvtLaunch(x,  xh,  (size_t)N_TOK * E_DIM);
    cvtLaunch(Wq, Wqkvh,                              (size_t)E_DIM * E_DIM);
    cvtLaunch(Wk, Wqkvh + (size_t)E_DIM * E_DIM,      (size_t)E_DIM * E_DIM);
    cvtLaunch(Wv, Wqkvh + (size_t)2 * E_DIM * E_DIM,  (size_t)E_DIM * E_DIM);
    cvtLaunch(Wo, Woh, (size_t)E_DIM * E_DIM);
    cvtLaunch(W1, W1h, (size_t)F_DIM * E_DIM);
    cvtLaunch(W2, W2h, (size_t)E_DIM * F_DIM);

    // --- fused QKV projection: [8192,1024] @ [3072,1024]^T -> qkv fp16 ---
    dim3 gqkv(QKV_LD / 128, N_TOK / 128, 1);
    gemm_fp16<128,128,64,32><<<gqkv, blk, SM_128>>>(
        xh, E_DIM, 0, 0,  Wqkvh, E_DIM, 0, 0,
        nullptr, qkv, QKV_LD, 0, 0,
        nullptr, nullptr, E_DIM, 1, 1.f, 0);

    // --- V transpose (f16 -> f16) ---
    transpose_v16<<<dim3(S_LEN / 32, HD_DIM / 32, BH_NUM), dim3(32, 8)>>>(qkv, Vth);

    // --- fused flash attention -> ah fp16 [b,s,(h,d)] ---
    flash_attn<<<dim3(S_LEN / FT_QT, BH_NUM), blk, FLASH_SMEM>>>(qkv, Vth, ah);

    // --- O projection + residual x ---
    dim3 gp(E_DIM / 128, N_TOK / 128, 1);
    gemm_fp16<128,128,64,32><<<gp, blk, SM_128>>>(
        ah, E_DIM, 0, 0,  Woh, E_DIM, 0, 0,
        res1, nullptr, E_DIM, 0, 0,
        x, nullptr, E_DIM, 1, 1.f, 0);

    // --- LN1 -> h (fp32 + fp16) ---
    layernorm_rows<<<N_TOK, 256>>>(res1, g1, b1, h, hh);

    // --- FFN1: relu(h @ W1^T + bb1) -> fp16 ---
    dim3 gf1(F_DIM / 128, N_TOK / 128, 1);
    gemm_fp16<128,128,64,32><<<gf1, blk, SM_128>>>(
        hh, E_DIM, 0, 0,  W1h, E_DIM, 0, 0,
        nullptr, fh, F_DIM, 0, 0,
        nullptr, bb1, E_DIM, 1, 1.f, 1);

    // --- FFN2: ffn @ W2^T + bb2 + h ---
    gemm_fp16<128,128,64,32><<<gp, blk, SM_128>>>(
        fh, F_DIM, 0, 0,  W2h, F_DIM, 0, 0,
        res2, nullptr, E_DIM, 0, 0,
        h, bb2, F_DIM, 1, 1.f, 0);

    // --- LN2 -> out ---
    layernorm_rows<<<N_TOK, 256>>>(res2, g2, b2, out, nullptr);
}